// round 1
// baseline (speedup 1.0000x reference)
#include <cuda_runtime.h>
#include <cuda_bf16.h>

#define Bb 4
#define Cc 256
#define Nn 4096
#define Gg 8
#define CPG 32            // channels per group
#define GSIZE (CPG*Nn)    // 131072
#define EPSf 1e-5f

// ---- scratch (device globals; no allocation allowed) ----
__device__ float g_xn[Bb*Cc*Nn];          // groupnorm output  [b][c][n]   16 MB
__device__ float g_qkv[Bb*3*Cc*Nn];       // qkv               [b][3c][n]  50 MB
__device__ float g_S[(size_t)Bb*Nn*Nn];   // scores/probs      [b][n][n]  256 MB
__device__ float g_ao[Bb*Cc*Nn];          // attention output  [b][c][n]   16 MB

// ============================================================
// GroupNorm: one block per (batch, group)
// ============================================================
__global__ void gn_kernel(const float* __restrict__ x,
                          const float* __restrict__ gamma,
                          const float* __restrict__ beta) {
    int bg = blockIdx.x;            // 0..31
    int b = bg / Gg, g = bg % Gg;
    size_t base = ((size_t)b * Cc + (size_t)g * CPG) * Nn;
    const float* xp = x + base;

    float s = 0.f, ss = 0.f;
    for (int i = threadIdx.x; i < GSIZE; i += blockDim.x) {
        float v = xp[i];
        s += v; ss += v * v;
    }
    __shared__ float sh_s[32], sh_ss[32];
    #pragma unroll
    for (int o = 16; o; o >>= 1) {
        s  += __shfl_down_sync(0xffffffffu, s,  o);
        ss += __shfl_down_sync(0xffffffffu, ss, o);
    }
    int wid = threadIdx.x >> 5, lid = threadIdx.x & 31;
    if (lid == 0) { sh_s[wid] = s; sh_ss[wid] = ss; }
    __syncthreads();
    int nw = blockDim.x >> 5;
    if (wid == 0) {
        s  = (lid < nw) ? sh_s[lid]  : 0.f;
        ss = (lid < nw) ? sh_ss[lid] : 0.f;
        #pragma unroll
        for (int o = 16; o; o >>= 1) {
            s  += __shfl_down_sync(0xffffffffu, s,  o);
            ss += __shfl_down_sync(0xffffffffu, ss, o);
        }
        if (lid == 0) { sh_s[0] = s; sh_ss[0] = ss; }
    }
    __syncthreads();
    float mean = sh_s[0] * (1.0f / GSIZE);
    float var  = sh_ss[0] * (1.0f / GSIZE) - mean * mean;
    float rstd = rsqrtf(var + EPSf);

    float* op = g_xn + base;
    for (int i = threadIdx.x; i < GSIZE; i += blockDim.x) {
        int ch = g * CPG + i / Nn;
        op[i] = (xp[i] - mean) * rstd * gamma[ch] + beta[ch];
    }
}

// ============================================================
// GEMM1: qkv[b][m][n] = W[m][k] * xn[b][k][n] + bias[m]
//   M=768, K=256, N=4096. Tiles 64x64x32, 256 thr, 4x4/thr.
// ============================================================
__global__ void gemm_qkv(const float* __restrict__ W,
                         const float* __restrict__ bias) {
    int bz = blockIdx.z;
    const float* Bp = g_xn + (size_t)bz * Cc * Nn;
    float* Cp = g_qkv + (size_t)bz * 3 * Cc * Nn;
    int bm = blockIdx.y * 64, bn = blockIdx.x * 64;

    __shared__ float As[32][68];   // As[k][m]
    __shared__ float Bs[32][68];   // Bs[k][n]
    float acc[4][4] = {};
    int tx = threadIdx.x % 16, ty = threadIdx.x / 16;

    for (int kk = 0; kk < Cc; kk += 32) {
        for (int i = threadIdx.x; i < 64 * 32; i += 256) {
            int m = i / 32, k = i % 32;
            As[k][m] = W[(size_t)(bm + m) * Cc + kk + k];
        }
        for (int i = threadIdx.x; i < 32 * 64; i += 256) {
            int k = i / 64, nn = i % 64;
            Bs[k][nn] = Bp[(size_t)(kk + k) * Nn + bn + nn];
        }
        __syncthreads();
        #pragma unroll
        for (int k = 0; k < 32; k++) {
            float4 a4 = *(const float4*)&As[k][ty * 4];
            float4 b4 = *(const float4*)&Bs[k][tx * 4];
            float ar[4] = {a4.x, a4.y, a4.z, a4.w};
            float br[4] = {b4.x, b4.y, b4.z, b4.w};
            #pragma unroll
            for (int i = 0; i < 4; i++)
                #pragma unroll
                for (int j = 0; j < 4; j++)
                    acc[i][j] = fmaf(ar[i], br[j], acc[i][j]);
        }
        __syncthreads();
    }
    #pragma unroll
    for (int i = 0; i < 4; i++) {
        int m = bm + ty * 4 + i;
        float bb = bias[m];
        float4 o = make_float4(acc[i][0] + bb, acc[i][1] + bb,
                               acc[i][2] + bb, acc[i][3] + bb);
        *(float4*)&Cp[(size_t)m * Nn + bn + tx * 4] = o;
    }
}

// ============================================================
// GEMM2: S[b][i][j] = (1/16) * sum_k q[b][k][i] * k[b][k][j]
//   Both operands K-major [256][4096]. M=N=4096, K=256.
// ============================================================
__global__ void gemm_scores() {
    int bz = blockIdx.z;
    const float* Q  = g_qkv + (size_t)bz * 3 * Cc * Nn;
    const float* Km = Q + (size_t)Cc * Nn;
    float* Sp = g_S + (size_t)bz * Nn * Nn;
    int bi = blockIdx.y * 64, bj = blockIdx.x * 64;

    __shared__ float As[32][68];   // As[k][i]
    __shared__ float Bs[32][68];   // Bs[k][j]
    float acc[4][4] = {};
    int tx = threadIdx.x % 16, ty = threadIdx.x / 16;

    for (int kk = 0; kk < Cc; kk += 32) {
        for (int i = threadIdx.x; i < 32 * 64; i += 256) {
            int k = i / 64, ii = i % 64;
            As[k][ii] = Q[(size_t)(kk + k) * Nn + bi + ii];
        }
        for (int i = threadIdx.x; i < 32 * 64; i += 256) {
            int k = i / 64, jj = i % 64;
            Bs[k][jj] = Km[(size_t)(kk + k) * Nn + bj + jj];
        }
        __syncthreads();
        #pragma unroll
        for (int k = 0; k < 32; k++) {
            float4 a4 = *(const float4*)&As[k][ty * 4];
            float4 b4 = *(const float4*)&Bs[k][tx * 4];
            float ar[4] = {a4.x, a4.y, a4.z, a4.w};
            float br[4] = {b4.x, b4.y, b4.z, b4.w};
            #pragma unroll
            for (int i = 0; i < 4; i++)
                #pragma unroll
                for (int j = 0; j < 4; j++)
                    acc[i][j] = fmaf(ar[i], br[j], acc[i][j]);
        }
        __syncthreads();
    }
    const float scale = 0.0625f;   // 1/sqrt(256)
    #pragma unroll
    for (int i = 0; i < 4; i++) {
        int ii = bi + ty * 4 + i;
        float4 o = make_float4(acc[i][0] * scale, acc[i][1] * scale,
                               acc[i][2] * scale, acc[i][3] * scale);
        *(float4*)&Sp[(size_t)ii * Nn + bj + tx * 4] = o;
    }
}

// ============================================================
// Softmax over each row of S (row length 4096), in place.
//   grid (4096, 4), 256 threads, 16 elements/thread in regs.
// ============================================================
__global__ void softmax_kernel() {
    float* r = g_S + ((size_t)blockIdx.y * Nn + blockIdx.x) * Nn;
    float v[16];
    float mx = -3.4e38f;
    #pragma unroll
    for (int i = 0; i < 16; i++) {
        v[i] = r[threadIdx.x + i * 256];
        mx = fmaxf(mx, v[i]);
    }
    __shared__ float sh[8];
    int wid = threadIdx.x >> 5, lid = threadIdx.x & 31;
    #pragma unroll
    for (int o = 16; o; o >>= 1) mx = fmaxf(mx, __shfl_xor_sync(0xffffffffu, mx, o));
    if (lid == 0) sh[wid] = mx;
    __syncthreads();
    mx = sh[0];
    #pragma unroll
    for (int w = 1; w < 8; w++) mx = fmaxf(mx, sh[w]);

    float s = 0.f;
    #pragma unroll
    for (int i = 0; i < 16; i++) {
        v[i] = __expf(v[i] - mx);
        s += v[i];
    }
    #pragma unroll
    for (int o = 16; o; o >>= 1) s += __shfl_xor_sync(0xffffffffu, s, o);
    __shared__ float shs[8];
    if (lid == 0) shs[wid] = s;
    __syncthreads();
    s = 0.f;
    #pragma unroll
    for (int w = 0; w < 8; w++) s += shs[w];
    float inv = 1.0f / s;
    #pragma unroll
    for (int i = 0; i < 16; i++) r[threadIdx.x + i * 256] = v[i] * inv;
}

// ============================================================
// GEMM3: ao[b][c][i] = sum_j v[b][c][j] * P[b][i][j]
//   A = V [256][4096] row-major (K=j contiguous), B = P^T.
//   M=256, N=4096, K=4096.
// ============================================================
__global__ void gemm_av() {
    int bz = blockIdx.z;
    const float* V = g_qkv + (size_t)bz * 3 * Cc * Nn + (size_t)2 * Cc * Nn;
    const float* P = g_S + (size_t)bz * Nn * Nn;
    float* Cp = g_ao + (size_t)bz * Cc * Nn;
    int bm = blockIdx.y * 64, bn = blockIdx.x * 64;

    __shared__ float As[32][68];   // As[k][m]  from V[m][k]
    __shared__ float Bs[32][68];   // Bs[k][n]  from P[n][k]
    float acc[4][4] = {};
    int tx = threadIdx.x % 16, ty = threadIdx.x / 16;

    for (int kk = 0; kk < Nn; kk += 32) {
        for (int i = threadIdx.x; i < 64 * 32; i += 256) {
            int m = i / 32, k = i % 32;
            As[k][m] = V[(size_t)(bm + m) * Nn + kk + k];
        }
        for (int i = threadIdx.x; i < 64 * 32; i += 256) {
            int nn = i / 32, k = i % 32;
            Bs[k][nn] = P[(size_t)(bn + nn) * Nn + kk + k];
        }
        __syncthreads();
        #pragma unroll
        for (int k = 0; k < 32; k++) {
            float4 a4 = *(const float4*)&As[k][ty * 4];
            float4 b4 = *(const float4*)&Bs[k][tx * 4];
            float ar[4] = {a4.x, a4.y, a4.z, a4.w};
            float br[4] = {b4.x, b4.y, b4.z, b4.w};
            #pragma unroll
            for (int i = 0; i < 4; i++)
                #pragma unroll
                for (int j = 0; j < 4; j++)
                    acc[i][j] = fmaf(ar[i], br[j], acc[i][j]);
        }
        __syncthreads();
    }
    #pragma unroll
    for (int i = 0; i < 4; i++) {
        int m = bm + ty * 4 + i;
        float4 o = make_float4(acc[i][0], acc[i][1], acc[i][2], acc[i][3]);
        *(float4*)&Cp[(size_t)m * Nn + bn + tx * 4] = o;
    }
}

// ============================================================
// GEMM4: out[b][o][i] = sum_c W[o][c]*ao[b][c][i] + ob[o] + x[b][o][i]
//   M=256, N=4096, K=256.
// ============================================================
__global__ void gemm_out(const float* __restrict__ W,
                         const float* __restrict__ ob,
                         const float* __restrict__ x,
                         float* __restrict__ out) {
    int bz = blockIdx.z;
    const float* Bp = g_ao + (size_t)bz * Cc * Nn;
    const float* xp = x   + (size_t)bz * Cc * Nn;
    float* Cp = out + (size_t)bz * Cc * Nn;
    int bm = blockIdx.y * 64, bn = blockIdx.x * 64;

    __shared__ float As[32][68];
    __shared__ float Bs[32][68];
    float acc[4][4] = {};
    int tx = threadIdx.x % 16, ty = threadIdx.x / 16;

    for (int kk = 0; kk < Cc; kk += 32) {
        for (int i = threadIdx.x; i < 64 * 32; i += 256) {
            int m = i / 32, k = i % 32;
            As[k][m] = W[(size_t)(bm + m) * Cc + kk + k];
        }
        for (int i = threadIdx.x; i < 32 * 64; i += 256) {
            int k = i / 64, nn = i % 64;
            Bs[k][nn] = Bp[(size_t)(kk + k) * Nn + bn + nn];
        }
        __syncthreads();
        #pragma unroll
        for (int k = 0; k < 32; k++) {
            float4 a4 = *(const float4*)&As[k][ty * 4];
            float4 b4 = *(const float4*)&Bs[k][tx * 4];
            float ar[4] = {a4.x, a4.y, a4.z, a4.w};
            float br[4] = {b4.x, b4.y, b4.z, b4.w};
            #pragma unroll
            for (int i = 0; i < 4; i++)
                #pragma unroll
                for (int j = 0; j < 4; j++)
                    acc[i][j] = fmaf(ar[i], br[j], acc[i][j]);
        }
        __syncthreads();
    }
    #pragma unroll
    for (int i = 0; i < 4; i++) {
        int m = bm + ty * 4 + i;
        float bb = ob[m];
        float4 res = *(const float4*)&xp[(size_t)m * Nn + bn + tx * 4];
        float4 o = make_float4(acc[i][0] + bb + res.x, acc[i][1] + bb + res.y,
                               acc[i][2] + bb + res.z, acc[i][3] + bb + res.w);
        *(float4*)&Cp[(size_t)m * Nn + bn + tx * 4] = o;
    }
}

// ============================================================
extern "C" void kernel_launch(void* const* d_in, const int* in_sizes, int n_in,
                              void* d_out, int out_size) {
    const float* x     = (const float*)d_in[0];
    const float* gamma = (const float*)d_in[1];
    const float* beta  = (const float*)d_in[2];
    const float* qkv_w = (const float*)d_in[3];
    const float* qkv_b = (const float*)d_in[4];
    const float* out_w = (const float*)d_in[5];
    const float* out_b = (const float*)d_in[6];
    float* out = (float*)d_out;

    gn_kernel<<<Bb * Gg, 1024>>>(x, gamma, beta);
    gemm_qkv<<<dim3(Nn / 64, 3 * Cc / 64, Bb), 256>>>(qkv_w, qkv_b);
    gemm_scores<<<dim3(Nn / 64, Nn / 64, Bb), 256>>>();
    softmax_kernel<<<dim3(Nn, Bb), 256>>>();
    gemm_av<<<dim3(Nn / 64, Cc / 64, Bb), 256>>>();
    gemm_out<<<dim3(Nn / 64, Cc / 64, Bb), 256>>>(out_w, out_b, x, out);
}

// round 7
// speedup vs baseline: 3.5438x; 3.5438x over previous
#include <cuda_runtime.h>
#include <cstdint>

#define Bb 4
#define Cc 256
#define Nn 4096
#define Gg 8
#define CPG 32
#define GSIZE (CPG*Nn)
#define EPSf 1e-5f

// ---- single scratch arena; device code only ever sees g_arena + offset ----
// offsets in floats
#define OFF_XN    ((size_t)0)
#define OFF_QKV   (OFF_XN   + (size_t)Bb*Cc*Nn)
#define OFF_S     (OFF_QKV  + (size_t)Bb*3*Cc*Nn)
#define OFF_AO    (OFF_S    + (size_t)Bb*Nn*Nn)
#define OFF_WQKVT (OFF_AO   + (size_t)Bb*Cc*Nn)
#define OFF_WOUTT (OFF_WQKVT+ (size_t)Cc*3*Cc)
#define OFF_VT    (OFF_WOUTT+ (size_t)Cc*Cc)
#define ARENA_SZ  (OFF_VT   + (size_t)Bb*Nn*Cc)

__device__ float g_arena[ARENA_SZ];

// ============================================================
// PTX helpers — macros only
// ============================================================
#define CPA16(smem_u32, gptr) \
    asm volatile("cp.async.cg.shared.global [%0], [%1], 16;" \
                 :: "r"(smem_u32), "l"(gptr))
#define CP_COMMIT() asm volatile("cp.async.commit_group;")
#define CP_WAIT0()  asm volatile("cp.async.wait_group 0;")

#define MMA_TF32(C, A, B) \
    asm volatile( \
        "mma.sync.aligned.m16n8k8.row.col.f32.tf32.tf32.f32 " \
        "{%0,%1,%2,%3},{%4,%5,%6,%7},{%8,%9},{%0,%1,%2,%3};" \
        : "+f"((C)[0]), "+f"((C)[1]), "+f"((C)[2]), "+f"((C)[3]) \
        : "r"((A)[0]), "r"((A)[1]), "r"((A)[2]), "r"((A)[3]), \
          "r"((B)[0]), "r"((B)[1]))

// ============================================================
// GroupNorm: one block per (batch, group). writes arena[OFF_XN].
// ============================================================
__global__ void gn_kernel(const float* __restrict__ x,
                          const float* __restrict__ gamma,
                          const float* __restrict__ beta) {
    int bg = blockIdx.x;
    int b = bg / Gg, g = bg % Gg;
    size_t base = ((size_t)b * Cc + (size_t)g * CPG) * Nn;
    const float* xp = x + base;

    float s = 0.f, ss = 0.f;
    for (int i = threadIdx.x; i < GSIZE; i += blockDim.x) {
        float v = xp[i];
        s += v; ss += v * v;
    }
    __shared__ float sh_s[32], sh_ss[32];
    #pragma unroll
    for (int o = 16; o; o >>= 1) {
        s  += __shfl_down_sync(0xffffffffu, s,  o);
        ss += __shfl_down_sync(0xffffffffu, ss, o);
    }
    int wid = threadIdx.x >> 5, lid = threadIdx.x & 31;
    if (lid == 0) { sh_s[wid] = s; sh_ss[wid] = ss; }
    __syncthreads();
    int nw = blockDim.x >> 5;
    if (wid == 0) {
        s  = (lid < nw) ? sh_s[lid]  : 0.f;
        ss = (lid < nw) ? sh_ss[lid] : 0.f;
        #pragma unroll
        for (int o = 16; o; o >>= 1) {
            s  += __shfl_down_sync(0xffffffffu, s,  o);
            ss += __shfl_down_sync(0xffffffffu, ss, o);
        }
        if (lid == 0) { sh_s[0] = s; sh_ss[0] = ss; }
    }
    __syncthreads();
    float mean = sh_s[0] * (1.0f / GSIZE);
    float var  = sh_ss[0] * (1.0f / GSIZE) - mean * mean;
    float rstd = rsqrtf(var + EPSf);

    float* op = g_arena + OFF_XN + base;
    for (int i = threadIdx.x; i < GSIZE; i += blockDim.x) {
        int ch = g * CPG + i / Nn;
        op[i] = (xp[i] - mean) * rstd * gamma[ch] + beta[ch];
    }
}

// ============================================================
// Tiled transpose into arena: out[k][m] = in[m][k].
//   in: external pointer if inExt != null, else arena + inOff.
// ============================================================
__global__ void transpose_b(const float* __restrict__ inExt, size_t inOff,
                            size_t outOff, int M, int K,
                            size_t inStride, size_t outStride) {
    __shared__ float t[32][33];
    const float* ip = (inExt ? inExt : g_arena + inOff) + (size_t)blockIdx.z * inStride;
    float* op = g_arena + outOff + (size_t)blockIdx.z * outStride;
    int k0 = blockIdx.x * 32, m0 = blockIdx.y * 32;
    int tx = threadIdx.x, ty = threadIdx.y;
    #pragma unroll
    for (int i = ty; i < 32; i += 8)
        t[i][tx] = ip[(size_t)(m0 + i) * K + k0 + tx];
    __syncthreads();
    #pragma unroll
    for (int i = ty; i < 32; i += 8)
        op[(size_t)(k0 + i) * M + m0 + tx] = t[tx][i];
}

// ============================================================
// Generic tf32 GEMM (NN form), operands in the arena:
//   C[m][n] = scale * sum_k At[k][m] * B[k][n] (+bias[m]) (+res[m][n])
//   CTA 128x128x16 double buffered, 8 warps of 64x32.
// ============================================================
#define BM 128
#define BN 128
#define BK 16
#define SA_LD 136
#define SB_LD 136

#define NN_LOAD_STAGE(buf, kk) do {                                            \
    uint32_t sa_ = (uint32_t)__cvta_generic_to_shared(&As[buf][0][0]);         \
    uint32_t sb_ = (uint32_t)__cvta_generic_to_shared(&Bs[buf][0][0]);         \
    { int id_ = tid;       int k_ = id_ >> 5, mq_ = id_ & 31;                  \
      CPA16(sa_ + (uint32_t)(k_ * SA_LD + mq_ * 4) * 4,                        \
            Ap + (size_t)((kk) + k_) * M + bm + mq_ * 4); }                    \
    { int id_ = tid + 256; int k_ = id_ >> 5, mq_ = id_ & 31;                  \
      CPA16(sa_ + (uint32_t)(k_ * SA_LD + mq_ * 4) * 4,                        \
            Ap + (size_t)((kk) + k_) * M + bm + mq_ * 4); }                    \
    { int id_ = tid;       int k_ = id_ >> 5, nq_ = id_ & 31;                  \
      CPA16(sb_ + (uint32_t)(k_ * SB_LD + nq_ * 4) * 4,                        \
            Bp + (size_t)((kk) + k_) * N + bn + nq_ * 4); }                    \
    { int id_ = tid + 256; int k_ = id_ >> 5, nq_ = id_ & 31;                  \
      CPA16(sb_ + (uint32_t)(k_ * SB_LD + nq_ * 4) * 4,                        \
            Bp + (size_t)((kk) + k_) * N + bn + nq_ * 4); }                    \
    CP_COMMIT();                                                               \
} while (0)

__global__ __launch_bounds__(256) void gemm_nn(
    size_t aOff, size_t bOff, size_t cOff, float* Cext,
    int M, int N, int K,
    size_t sAt, size_t sB, size_t sC,
    const float* __restrict__ bias,
    const float* __restrict__ resExt, size_t sRes,
    float scale)
{
    __shared__ float As[2][BK][SA_LD];
    __shared__ float Bs[2][BK][SB_LD];

    int bz = blockIdx.z;
    const float* Ap = g_arena + aOff + (size_t)bz * sAt;
    const float* Bp = g_arena + bOff + (size_t)bz * sB;
    float* Cp = (Cext ? Cext : g_arena + cOff) + (size_t)bz * sC;
    int bm = blockIdx.y * BM, bn = blockIdx.x * BN;
    int tid = threadIdx.x, lane = tid & 31, wid = tid >> 5;
    int wm = (wid & 1) * 64, wn = (wid >> 1) * 32;

    float acc[4][4][4];
    #pragma unroll
    for (int i = 0; i < 4; i++)
        #pragma unroll
        for (int j = 0; j < 4; j++)
            #pragma unroll
            for (int r = 0; r < 4; r++) acc[i][j][r] = 0.f;

    int steps = K / BK;
    NN_LOAD_STAGE(0, 0);

    for (int it = 0; it < steps; it++) {
        CP_WAIT0();
        __syncthreads();
        if (it + 1 < steps) {
            int buf = (it + 1) & 1, kk = (it + 1) * BK;
            NN_LOAD_STAGE(buf, kk);
        }

        int cur = it & 1;
        #pragma unroll
        for (int k0 = 0; k0 < BK; k0 += 8) {
            uint32_t afr[4][4], bfr[4][2];
            int kr = k0 + (lane & 3);
            int mrow = (lane >> 2);
            #pragma unroll
            for (int mt = 0; mt < 4; mt++) {
                int m0 = wm + mt * 16 + mrow;
                afr[mt][0] = __float_as_uint(As[cur][kr][m0]);
                afr[mt][1] = __float_as_uint(As[cur][kr][m0 + 8]);
                afr[mt][2] = __float_as_uint(As[cur][kr + 4][m0]);
                afr[mt][3] = __float_as_uint(As[cur][kr + 4][m0 + 8]);
            }
            #pragma unroll
            for (int nt = 0; nt < 4; nt++) {
                int n0 = wn + nt * 8 + (lane >> 2);
                bfr[nt][0] = __float_as_uint(Bs[cur][kr][n0]);
                bfr[nt][1] = __float_as_uint(Bs[cur][kr + 4][n0]);
            }
            #pragma unroll
            for (int mt = 0; mt < 4; mt++)
                #pragma unroll
                for (int nt = 0; nt < 4; nt++)
                    MMA_TF32(acc[mt][nt], afr[mt], bfr[nt]);
        }
    }

    #pragma unroll
    for (int mt = 0; mt < 4; mt++) {
        int r0 = bm + wm + mt * 16 + (lane >> 2);
        float b0f = bias ? bias[r0] : 0.f;
        float b1f = bias ? bias[r0 + 8] : 0.f;
        #pragma unroll
        for (int nt = 0; nt < 4; nt++) {
            int cc = bn + wn + nt * 8 + 2 * (lane & 3);
            float v0 = acc[mt][nt][0] * scale + b0f;
            float v1 = acc[mt][nt][1] * scale + b0f;
            float v2 = acc[mt][nt][2] * scale + b1f;
            float v3 = acc[mt][nt][3] * scale + b1f;
            if (resExt) {
                const float* rp = resExt + (size_t)bz * sRes;
                float2 ra = *(const float2*)&rp[(size_t)r0 * N + cc];
                float2 rb = *(const float2*)&rp[(size_t)(r0 + 8) * N + cc];
                v0 += ra.x; v1 += ra.y; v2 += rb.x; v3 += rb.y;
            }
            *(float2*)&Cp[(size_t)r0 * N + cc]       = make_float2(v0, v1);
            *(float2*)&Cp[(size_t)(r0 + 8) * N + cc] = make_float2(v2, v3);
        }
    }
}

// ============================================================
// attn*V GEMM:  ao[c][i] = sum_j Vt[j][c] * P[i][j]  (arena only)
// ============================================================
#define SB2_LD 20

#define AV_LOAD_STAGE(buf, kk) do {                                            \
    uint32_t sa_ = (uint32_t)__cvta_generic_to_shared(&As[buf][0][0]);         \
    uint32_t sb_ = (uint32_t)__cvta_generic_to_shared(&Bs[buf][0][0]);         \
    { int id_ = tid;       int k_ = id_ >> 5, mq_ = id_ & 31;                  \
      CPA16(sa_ + (uint32_t)(k_ * SA_LD + mq_ * 4) * 4,                        \
            Ap + (size_t)((kk) + k_) * Cc + bm + mq_ * 4); }                   \
    { int id_ = tid + 256; int k_ = id_ >> 5, mq_ = id_ & 31;                  \
      CPA16(sa_ + (uint32_t)(k_ * SA_LD + mq_ * 4) * 4,                        \
            Ap + (size_t)((kk) + k_) * Cc + bm + mq_ * 4); }                   \
    { int id_ = tid;       int n_ = id_ >> 2, kq_ = id_ & 3;                   \
      CPA16(sb_ + (uint32_t)(n_ * SB2_LD + kq_ * 4) * 4,                       \
            Pp + (size_t)(bn + n_) * Nn + (kk) + kq_ * 4); }                   \
    { int id_ = tid + 256; int n_ = id_ >> 2, kq_ = id_ & 3;                   \
      CPA16(sb_ + (uint32_t)(n_ * SB2_LD + kq_ * 4) * 4,                       \
            Pp + (size_t)(bn + n_) * Nn + (kk) + kq_ * 4); }                   \
    CP_COMMIT();                                                               \
} while (0)

__global__ __launch_bounds__(256) void gemm_av() {
    __shared__ float As[2][BK][SA_LD];
    __shared__ float Bs[2][BN][SB2_LD];

    int bz = blockIdx.z;
    const float* Ap = g_arena + OFF_VT + (size_t)bz * Nn * Cc;
    const float* Pp = g_arena + OFF_S + (size_t)bz * Nn * Nn;
    float* Cp = g_arena + OFF_AO + (size_t)bz * Cc * Nn;
    int bm = blockIdx.y * BM, bn = blockIdx.x * BN;
    int tid = threadIdx.x, lane = tid & 31, wid = tid >> 5;
    int wm = (wid & 1) * 64, wn = (wid >> 1) * 32;

    float acc[4][4][4];
    #pragma unroll
    for (int i = 0; i < 4; i++)
        #pragma unroll
        for (int j = 0; j < 4; j++)
            #pragma unroll
            for (int r = 0; r < 4; r++) acc[i][j][r] = 0.f;

    int steps = Nn / BK;
    AV_LOAD_STAGE(0, 0);

    for (int it = 0; it < steps; it++) {
        CP_WAIT0();
        __syncthreads();
        if (it + 1 < steps) {
            int buf = (it + 1) & 1, kk = (it + 1) * BK;
            AV_LOAD_STAGE(buf, kk);
        }

        int cur = it & 1;
        #pragma unroll
        for (int k0 = 0; k0 < BK; k0 += 8) {
            uint32_t afr[4][4], bfr[4][2];
            int kr = k0 + (lane & 3);
            int mrow = (lane >> 2);
            #pragma unroll
            for (int mt = 0; mt < 4; mt++) {
                int m0 = wm + mt * 16 + mrow;
                afr[mt][0] = __float_as_uint(As[cur][kr][m0]);
                afr[mt][1] = __float_as_uint(As[cur][kr][m0 + 8]);
                afr[mt][2] = __float_as_uint(As[cur][kr + 4][m0]);
                afr[mt][3] = __float_as_uint(As[cur][kr + 4][m0 + 8]);
            }
            #pragma unroll
            for (int nt = 0; nt < 4; nt++) {
                int n0 = wn + nt * 8 + (lane >> 2);
                bfr[nt][0] = __float_as_uint(Bs[cur][n0][kr]);
                bfr[nt][1] = __float_as_uint(Bs[cur][n0][kr + 4]);
            }
            #pragma unroll
            for (int mt = 0; mt < 4; mt++)
                #pragma unroll
                for (int nt = 0; nt < 4; nt++)
                    MMA_TF32(acc[mt][nt], afr[mt], bfr[nt]);
        }
    }

    #pragma unroll
    for (int mt = 0; mt < 4; mt++) {
        int r0 = bm + wm + mt * 16 + (lane >> 2);
        #pragma unroll
        for (int nt = 0; nt < 4; nt++) {
            int cc = bn + wn + nt * 8 + 2 * (lane & 3);
            *(float2*)&Cp[(size_t)r0 * Nn + cc] =
                make_float2(acc[mt][nt][0], acc[mt][nt][1]);
            *(float2*)&Cp[(size_t)(r0 + 8) * Nn + cc] =
                make_float2(acc[mt][nt][2], acc[mt][nt][3]);
        }
    }
}

// ============================================================
// Softmax over each row of S (row length 4096), in place in arena.
// ============================================================
__global__ void softmax_kernel() {
    float* r = g_arena + OFF_S + ((size_t)blockIdx.y * Nn + blockIdx.x) * Nn;
    float v[16];
    float mx = -3.4e38f;
    #pragma unroll
    for (int i = 0; i < 16; i++) {
        v[i] = r[threadIdx.x + i * 256];
        mx = fmaxf(mx, v[i]);
    }
    __shared__ float sh[8];
    int wid = threadIdx.x >> 5, lid = threadIdx.x & 31;
    #pragma unroll
    for (int o = 16; o; o >>= 1) mx = fmaxf(mx, __shfl_xor_sync(0xffffffffu, mx, o));
    if (lid == 0) sh[wid] = mx;
    __syncthreads();
    mx = sh[0];
    #pragma unroll
    for (int w = 1; w < 8; w++) mx = fmaxf(mx, sh[w]);

    float s = 0.f;
    #pragma unroll
    for (int i = 0; i < 16; i++) {
        v[i] = __expf(v[i] - mx);
        s += v[i];
    }
    #pragma unroll
    for (int o = 16; o; o >>= 1) s += __shfl_xor_sync(0xffffffffu, s, o);
    __shared__ float shs[8];
    if (lid == 0) shs[wid] = s;
    __syncthreads();
    s = 0.f;
    #pragma unroll
    for (int w = 0; w < 8; w++) s += shs[w];
    float inv = 1.0f / s;
    #pragma unroll
    for (int i = 0; i < 16; i++) r[threadIdx.x + i * 256] = v[i] * inv;
}

// ============================================================
extern "C" void kernel_launch(void* const* d_in, const int* in_sizes, int n_in,
                              void* d_out, int out_size) {
    const float* x     = (const float*)d_in[0];
    const float* gamma = (const float*)d_in[1];
    const float* beta  = (const float*)d_in[2];
    const float* qkv_w = (const float*)d_in[3];
    const float* qkv_b = (const float*)d_in[4];
    const float* out_w = (const float*)d_in[5];
    const float* out_b = (const float*)d_in[6];
    float* out = (float*)d_out;

    gn_kernel<<<Bb * Gg, 1024>>>(x, gamma, beta);

    // weight transposes (tiny): external in -> arena out
    transpose_b<<<dim3(Cc / 32, 3 * Cc / 32, 1), dim3(32, 8)>>>(
        qkv_w, 0, OFF_WQKVT, 3 * Cc, Cc, 0, 0);
    transpose_b<<<dim3(Cc / 32, Cc / 32, 1), dim3(32, 8)>>>(
        out_w, 0, OFF_WOUTT, Cc, Cc, 0, 0);

    // qkv = Wqkv * xn + b   (M=768, N=4096, K=256)
    gemm_nn<<<dim3(Nn / BN, 3 * Cc / BM, Bb), 256>>>(
        OFF_WQKVT, OFF_XN, OFF_QKV, nullptr,
        3 * Cc, Nn, Cc,
        0, (size_t)Cc * Nn, (size_t)3 * Cc * Nn,
        qkv_b, nullptr, 0, 1.0f);

    // S = (Q^T K) / 16      (M=N=4096, K=256)
    gemm_nn<<<dim3(Nn / BN, Nn / BM, Bb), 256>>>(
        OFF_QKV, OFF_QKV + (size_t)Cc * Nn, OFF_S, nullptr,
        Nn, Nn, Cc,
        (size_t)3 * Cc * Nn, (size_t)3 * Cc * Nn, (size_t)Nn * Nn,
        nullptr, nullptr, 0, 0.0625f);

    softmax_kernel<<<dim3(Nn, Bb), 256>>>();

    // transpose V (arena -> arena): [c][j] -> Vt [j][c], per batch
    transpose_b<<<dim3(Nn / 32, Cc / 32, Bb), dim3(32, 8)>>>(
        nullptr, OFF_QKV + (size_t)2 * Cc * Nn, OFF_VT,
        Cc, Nn, (size_t)3 * Cc * Nn, (size_t)Nn * Cc);

    // ao = P * V^T          (M=256, N=4096, K=4096)
    gemm_av<<<dim3(Nn / BN, Cc / BM, Bb), 256>>>();

    // out = Wout * ao + b + x  (M=256, N=4096, K=256)
    gemm_nn<<<dim3(Nn / BN, Cc / BM, Bb), 256>>>(
        OFF_WOUTT, OFF_AO, 0, out,
        Cc, Nn, Cc,
        0, (size_t)Cc * Nn, (size_t)Cc * Nn,
        out_b, x, (size_t)Cc * Nn, 1.0f);
}

// round 9
// speedup vs baseline: 6.0045x; 1.6944x over previous
#include <cuda_runtime.h>
#include <cuda_fp16.h>
#include <cstdint>

#define Bb 4
#define Cc 256
#define Nn 4096
#define Gg 8
#define CPG 32
#define GSIZE (CPG*Nn)
#define EPSf 1e-5f

// ---- fp16 arena (halfs) ----
#define OFF_XN16   ((size_t)0)
#define OFF_QKV16  (OFF_XN16  + (size_t)Bb*Cc*Nn)
#define OFF_VT16   (OFF_QKV16 + (size_t)Bb*3*Cc*Nn)
#define OFF_P16    (OFF_VT16  + (size_t)Bb*Nn*Cc)
#define OFF_AO16   (OFF_P16   + (size_t)Bb*Nn*Nn)
#define OFF_WQ16   (OFF_AO16  + (size_t)Bb*Cc*Nn)
#define OFF_WO16   (OFF_WQ16  + (size_t)Cc*3*Cc)
#define H_SZ       (OFF_WO16  + (size_t)Cc*Cc)

__device__ __align__(16) __half g_h[H_SZ];
__device__ float g_S[(size_t)Bb*Nn*Nn];      // scores fp32

// ============================================================
// PTX macros
// ============================================================
#define CPA16(smem_u32, gptr) \
    asm volatile("cp.async.cg.shared.global [%0], [%1], 16;" \
                 :: "r"(smem_u32), "l"(gptr))
#define CP_COMMIT() asm volatile("cp.async.commit_group;")
#define CP_WAIT0()  asm volatile("cp.async.wait_group 0;")

#define LDSM4T(R, addr) \
    asm volatile("ldmatrix.sync.aligned.m8n8.x4.trans.shared.b16 {%0,%1,%2,%3}, [%4];" \
        : "=r"((R)[0]), "=r"((R)[1]), "=r"((R)[2]), "=r"((R)[3]) : "r"(addr))
#define LDSM4N(R, addr) \
    asm volatile("ldmatrix.sync.aligned.m8n8.x4.shared.b16 {%0,%1,%2,%3}, [%4];" \
        : "=r"((R)[0]), "=r"((R)[1]), "=r"((R)[2]), "=r"((R)[3]) : "r"(addr))

#define MMA16(C, A, B) \
    asm volatile( \
        "mma.sync.aligned.m16n8k16.row.col.f32.f16.f16.f32 " \
        "{%0,%1,%2,%3},{%4,%5,%6,%7},{%8,%9},{%0,%1,%2,%3};" \
        : "+f"((C)[0]), "+f"((C)[1]), "+f"((C)[2]), "+f"((C)[3]) \
        : "r"((A)[0]), "r"((A)[1]), "r"((A)[2]), "r"((A)[3]), \
          "r"((B)[0]), "r"((B)[1]))

// ============================================================
// GroupNorm -> fp16 xn
// ============================================================
__global__ void gn_kernel(const float* __restrict__ x,
                          const float* __restrict__ gamma,
                          const float* __restrict__ beta) {
    int bg = blockIdx.x;
    int b = bg / Gg, g = bg % Gg;
    size_t base = ((size_t)b * Cc + (size_t)g * CPG) * Nn;
    const float* xp = x + base;

    float s = 0.f, ss = 0.f;
    for (int i = threadIdx.x; i < GSIZE; i += blockDim.x) {
        float v = xp[i];
        s += v; ss += v * v;
    }
    __shared__ float sh_s[32], sh_ss[32];
    #pragma unroll
    for (int o = 16; o; o >>= 1) {
        s  += __shfl_down_sync(0xffffffffu, s,  o);
        ss += __shfl_down_sync(0xffffffffu, ss, o);
    }
    int wid = threadIdx.x >> 5, lid = threadIdx.x & 31;
    if (lid == 0) { sh_s[wid] = s; sh_ss[wid] = ss; }
    __syncthreads();
    int nw = blockDim.x >> 5;
    if (wid == 0) {
        s  = (lid < nw) ? sh_s[lid]  : 0.f;
        ss = (lid < nw) ? sh_ss[lid] : 0.f;
        #pragma unroll
        for (int o = 16; o; o >>= 1) {
            s  += __shfl_down_sync(0xffffffffu, s,  o);
            ss += __shfl_down_sync(0xffffffffu, ss, o);
        }
        if (lid == 0) { sh_s[0] = s; sh_ss[0] = ss; }
    }
    __syncthreads();
    float mean = sh_s[0] * (1.0f / GSIZE);
    float var  = sh_ss[0] * (1.0f / GSIZE) - mean * mean;
    float rstd = rsqrtf(var + EPSf);

    __half* op = g_h + OFF_XN16 + base;
    for (int i = threadIdx.x; i < GSIZE; i += blockDim.x) {
        int ch = g * CPG + i / Nn;
        op[i] = __float2half((xp[i] - mean) * rstd * gamma[ch] + beta[ch]);
    }
}

// ============================================================
// transpose fp32 ext [M][K] -> fp16 arena [K][M]
// ============================================================
__global__ void tr_f2h(const float* __restrict__ in, size_t outOff, int M, int K) {
    __shared__ float t[32][33];
    int k0 = blockIdx.x * 32, m0 = blockIdx.y * 32;
    int tx = threadIdx.x, ty = threadIdx.y;
    #pragma unroll
    for (int i = ty; i < 32; i += 8)
        t[i][tx] = in[(size_t)(m0 + i) * K + k0 + tx];
    __syncthreads();
    __half* op = g_h + outOff;
    #pragma unroll
    for (int i = ty; i < 32; i += 8)
        op[(size_t)(k0 + i) * M + m0 + tx] = __float2half(t[tx][i]);
}

// ============================================================
// transpose fp16 arena [M][K] -> fp16 arena [K][M] (per batch z)
// ============================================================
__global__ void tr_h2h(size_t inOff, size_t outOff, int M, int K,
                       size_t inStride, size_t outStride) {
    __shared__ __half t[32][34];
    const __half* ip = g_h + inOff + (size_t)blockIdx.z * inStride;
    __half* op = g_h + outOff + (size_t)blockIdx.z * outStride;
    int k0 = blockIdx.x * 32, m0 = blockIdx.y * 32;
    int tx = threadIdx.x, ty = threadIdx.y;
    #pragma unroll
    for (int i = ty; i < 32; i += 8)
        t[i][tx] = ip[(size_t)(m0 + i) * K + k0 + tx];
    __syncthreads();
    #pragma unroll
    for (int i = ty; i < 32; i += 8)
        op[(size_t)(k0 + i) * M + m0 + tx] = t[tx][i];
}

// ============================================================
// fp16 GEMM (A-trans, B-trans): C[m][n] = sum_k At[k][m]*B[k][n]
//   modes: 0 -> fp16 arena (+bias); 1 -> fp32 g_S (*scale);
//          2 -> fp32 ext (+bias +res)
//   CTA 128x128x32(halfs), 8 warps of 64x32, double buffered.
// ============================================================
#define BM 128
#define BN 128
#define HBK 32
#define HLD 136    // padded stride (halfs)

#define H_LOAD(buf, kk) do {                                                   \
    uint32_t sa_ = (uint32_t)__cvta_generic_to_shared(&As[buf][0][0]);         \
    uint32_t sb_ = (uint32_t)__cvta_generic_to_shared(&Bs[buf][0][0]);         \
    { int id_ = tid;       int k_ = id_ >> 4, mq_ = id_ & 15;                  \
      CPA16(sa_ + (uint32_t)(k_ * HLD + mq_ * 8) * 2,                          \
            Ap + (size_t)((kk) + k_) * M + bm + mq_ * 8); }                    \
    { int id_ = tid + 256; int k_ = id_ >> 4, mq_ = id_ & 15;                  \
      CPA16(sa_ + (uint32_t)(k_ * HLD + mq_ * 8) * 2,                          \
            Ap + (size_t)((kk) + k_) * M + bm + mq_ * 8); }                    \
    { int id_ = tid;       int k_ = id_ >> 4, nq_ = id_ & 15;                  \
      CPA16(sb_ + (uint32_t)(k_ * HLD + nq_ * 8) * 2,                          \
            Bp + (size_t)((kk) + k_) * N + bn + nq_ * 8); }                    \
    { int id_ = tid + 256; int k_ = id_ >> 4, nq_ = id_ & 15;                  \
      CPA16(sb_ + (uint32_t)(k_ * HLD + nq_ * 8) * 2,                          \
            Bp + (size_t)((kk) + k_) * N + bn + nq_ * 8); }                    \
    CP_COMMIT();                                                               \
} while (0)

__global__ __launch_bounds__(256) void gemm_h(
    size_t aOff, size_t bOff, size_t cOff, float* Cext,
    int M, int N, int K,
    size_t sA, size_t sB, size_t sC,
    const float* __restrict__ bias,
    const float* __restrict__ resExt, size_t sRes,
    float scale, int mode)
{
    __shared__ __half As[2][HBK][HLD];
    __shared__ __half Bs[2][HBK][HLD];

    int bz = blockIdx.z;
    const __half* Ap = g_h + aOff + (size_t)bz * sA;
    const __half* Bp = g_h + bOff + (size_t)bz * sB;
    int bm = blockIdx.y * BM, bn = blockIdx.x * BN;
    int tid = threadIdx.x, lane = tid & 31, wid = tid >> 5;
    int wm = (wid & 1) * 64, wn = (wid >> 1) * 32;

    float acc[4][4][4];
    #pragma unroll
    for (int i = 0; i < 4; i++)
        #pragma unroll
        for (int j = 0; j < 4; j++)
            #pragma unroll
            for (int r = 0; r < 4; r++) acc[i][j][r] = 0.f;

    // ldmatrix lane-address components
    int aRow = ((lane >> 4) << 3) + (lane & 7);      // + ks
    int aCol = ((lane >> 3) & 1) * 8;                // + m_base
    int bRow = ((lane >> 3) & 1) * 8 + (lane & 7);   // + ks
    int bCol = (lane >> 4) * 8;                      // + n_base

    int steps = K / HBK;
    H_LOAD(0, 0);

    for (int it = 0; it < steps; it++) {
        CP_WAIT0();
        __syncthreads();
        if (it + 1 < steps) {
            int buf = (it + 1) & 1, kk = (it + 1) * HBK;
            H_LOAD(buf, kk);
        }
        int cur = it & 1;
        uint32_t sa = (uint32_t)__cvta_generic_to_shared(&As[cur][0][0]);
        uint32_t sb = (uint32_t)__cvta_generic_to_shared(&Bs[cur][0][0]);

        #pragma unroll
        for (int ks = 0; ks < HBK; ks += 16) {
            uint32_t a[4][4], b[4][2];
            #pragma unroll
            for (int mt = 0; mt < 4; mt++) {
                uint32_t ad = sa + (uint32_t)((ks + aRow) * HLD + wm + mt * 16 + aCol) * 2;
                LDSM4T(a[mt], ad);
            }
            #pragma unroll
            for (int np = 0; np < 2; np++) {
                uint32_t bd = sb + (uint32_t)((ks + bRow) * HLD + wn + np * 16 + bCol) * 2;
                uint32_t rr[4];
                LDSM4T(rr, bd);
                b[np * 2][0] = rr[0]; b[np * 2][1] = rr[1];
                b[np * 2 + 1][0] = rr[2]; b[np * 2 + 1][1] = rr[3];
            }
            #pragma unroll
            for (int mt = 0; mt < 4; mt++)
                #pragma unroll
                for (int nt = 0; nt < 4; nt++)
                    MMA16(acc[mt][nt], a[mt], b[nt]);
        }
    }

    // epilogue
    #pragma unroll
    for (int mt = 0; mt < 4; mt++) {
        int r0 = bm + wm + mt * 16 + (lane >> 2);
        float b0f = bias ? bias[r0] : 0.f;
        float b1f = bias ? bias[r0 + 8] : 0.f;
        #pragma unroll
        for (int nt = 0; nt < 4; nt++) {
            int cc = bn + wn + nt * 8 + 2 * (lane & 3);
            float v0 = acc[mt][nt][0], v1 = acc[mt][nt][1];
            float v2 = acc[mt][nt][2], v3 = acc[mt][nt][3];
            if (mode == 0) {
                __half* Ch = g_h + cOff + (size_t)bz * sC;
                *(__half2*)&Ch[(size_t)r0 * N + cc] =
                    __floats2half2_rn(v0 + b0f, v1 + b0f);
                *(__half2*)&Ch[(size_t)(r0 + 8) * N + cc] =
                    __floats2half2_rn(v2 + b1f, v3 + b1f);
            } else if (mode == 1) {
                float* Sp = g_S + (size_t)bz * Nn * Nn;
                *(float2*)&Sp[(size_t)r0 * N + cc] = make_float2(v0 * scale, v1 * scale);
                *(float2*)&Sp[(size_t)(r0 + 8) * N + cc] = make_float2(v2 * scale, v3 * scale);
            } else {
                float* Cp = Cext + (size_t)bz * sC;
                const float* rp = resExt + (size_t)bz * sRes;
                float2 ra = *(const float2*)&rp[(size_t)r0 * N + cc];
                float2 rb = *(const float2*)&rp[(size_t)(r0 + 8) * N + cc];
                *(float2*)&Cp[(size_t)r0 * N + cc] =
                    make_float2(v0 + b0f + ra.x, v1 + b0f + ra.y);
                *(float2*)&Cp[(size_t)(r0 + 8) * N + cc] =
                    make_float2(v2 + b1f + rb.x, v3 + b1f + rb.y);
            }
        }
    }
}

// ============================================================
// attn*V fp16:  ao16[c][i] = sum_j Vt16[j][c] * P16[i][j]
//   A trans as above; B non-trans from P stored [n=i][k=j].
// ============================================================
#define PLD 40

#define AV_LOAD(buf, kk) do {                                                  \
    uint32_t sa_ = (uint32_t)__cvta_generic_to_shared(&As[buf][0][0]);         \
    uint32_t sp_ = (uint32_t)__cvta_generic_to_shared(&Ps[buf][0][0]);         \
    { int id_ = tid;       int k_ = id_ >> 4, mq_ = id_ & 15;                  \
      CPA16(sa_ + (uint32_t)(k_ * HLD + mq_ * 8) * 2,                          \
            Ap + (size_t)((kk) + k_) * Cc + bm + mq_ * 8); }                   \
    { int id_ = tid + 256; int k_ = id_ >> 4, mq_ = id_ & 15;                  \
      CPA16(sa_ + (uint32_t)(k_ * HLD + mq_ * 8) * 2,                          \
            Ap + (size_t)((kk) + k_) * Cc + bm + mq_ * 8); }                   \
    { int id_ = tid;       int n_ = id_ >> 2, kq_ = id_ & 3;                   \
      CPA16(sp_ + (uint32_t)(n_ * PLD + kq_ * 8) * 2,                          \
            Pp + (size_t)(bn + n_) * Nn + (kk) + kq_ * 8); }                   \
    { int id_ = tid + 256; int n_ = id_ >> 2, kq_ = id_ & 3;                   \
      CPA16(sp_ + (uint32_t)(n_ * PLD + kq_ * 8) * 2,                          \
            Pp + (size_t)(bn + n_) * Nn + (kk) + kq_ * 8); }                   \
    CP_COMMIT();                                                               \
} while (0)

__global__ __launch_bounds__(256) void gemm_av_h() {
    __shared__ __half As[2][HBK][HLD];
    __shared__ __half Ps[2][BN][PLD];

    int bz = blockIdx.z;
    const __half* Ap = g_h + OFF_VT16 + (size_t)bz * Nn * Cc;
    const __half* Pp = g_h + OFF_P16 + (size_t)bz * Nn * Nn;
    __half* Cp = g_h + OFF_AO16 + (size_t)bz * Cc * Nn;
    int bm = blockIdx.y * BM, bn = blockIdx.x * BN;
    int tid = threadIdx.x, lane = tid & 31, wid = tid >> 5;
    int wm = (wid & 1) * 64, wn = (wid >> 1) * 32;

    float acc[4][4][4];
    #pragma unroll
    for (int i = 0; i < 4; i++)
        #pragma unroll
        for (int j = 0; j < 4; j++)
            #pragma unroll
            for (int r = 0; r < 4; r++) acc[i][j][r] = 0.f;

    int aRow = ((lane >> 4) << 3) + (lane & 7);
    int aCol = ((lane >> 3) & 1) * 8;
    int pRow = (lane >> 4) * 8 + (lane & 7);       // + n_base
    int pCol = ((lane >> 3) & 1) * 8;              // + ks

    int steps = Nn / HBK;
    AV_LOAD(0, 0);

    for (int it = 0; it < steps; it++) {
        CP_WAIT0();
        __syncthreads();
        if (it + 1 < steps) {
            int buf = (it + 1) & 1, kk = (it + 1) * HBK;
            AV_LOAD(buf, kk);
        }
        int cur = it & 1;
        uint32_t sa = (uint32_t)__cvta_generic_to_shared(&As[cur][0][0]);
        uint32_t sp = (uint32_t)__cvta_generic_to_shared(&Ps[cur][0][0]);

        #pragma unroll
        for (int ks = 0; ks < HBK; ks += 16) {
            uint32_t a[4][4], b[4][2];
            #pragma unroll
            for (int mt = 0; mt < 4; mt++) {
                uint32_t ad = sa + (uint32_t)((ks + aRow) * HLD + wm + mt * 16 + aCol) * 2;
                LDSM4T(a[mt], ad);
            }
            #pragma unroll
            for (int np = 0; np < 2; np++) {
                uint32_t pd = sp + (uint32_t)((wn + np * 16 + pRow) * PLD + ks + pCol) * 2;
                uint32_t rr[4];
                LDSM4N(rr, pd);
                b[np * 2][0] = rr[0]; b[np * 2][1] = rr[1];
                b[np * 2 + 1][0] = rr[2]; b[np * 2 + 1][1] = rr[3];
            }
            #pragma unroll
            for (int mt = 0; mt < 4; mt++)
                #pragma unroll
                for (int nt = 0; nt < 4; nt++)
                    MMA16(acc[mt][nt], a[mt], b[nt]);
        }
    }

    #pragma unroll
    for (int mt = 0; mt < 4; mt++) {
        int r0 = bm + wm + mt * 16 + (lane >> 2);
        #pragma unroll
        for (int nt = 0; nt < 4; nt++) {
            int cc = bn + wn + nt * 8 + 2 * (lane & 3);
            *(__half2*)&Cp[(size_t)r0 * Nn + cc] =
                __floats2half2_rn(acc[mt][nt][0], acc[mt][nt][1]);
            *(__half2*)&Cp[(size_t)(r0 + 8) * Nn + cc] =
                __floats2half2_rn(acc[mt][nt][2], acc[mt][nt][3]);
        }
    }
}

// ============================================================
// Softmax: read fp32 S row, write fp16 P row.
// ============================================================
__global__ void softmax_kernel() {
    const float* r = g_S + ((size_t)blockIdx.y * Nn + blockIdx.x) * Nn;
    __half* p = g_h + OFF_P16 + ((size_t)blockIdx.y * Nn + blockIdx.x) * Nn;
    float v[16];
    float mx = -3.4e38f;
    #pragma unroll
    for (int i = 0; i < 16; i++) {
        v[i] = r[threadIdx.x + i * 256];
        mx = fmaxf(mx, v[i]);
    }
    __shared__ float sh[8];
    int wid = threadIdx.x >> 5, lid = threadIdx.x & 31;
    #pragma unroll
    for (int o = 16; o; o >>= 1) mx = fmaxf(mx, __shfl_xor_sync(0xffffffffu, mx, o));
    if (lid == 0) sh[wid] = mx;
    __syncthreads();
    mx = sh[0];
    #pragma unroll
    for (int w = 1; w < 8; w++) mx = fmaxf(mx, sh[w]);

    float s = 0.f;
    #pragma unroll
    for (int i = 0; i < 16; i++) {
        v[i] = __expf(v[i] - mx);
        s += v[i];
    }
    #pragma unroll
    for (int o = 16; o; o >>= 1) s += __shfl_xor_sync(0xffffffffu, s, o);
    __shared__ float shs[8];
    if (lid == 0) shs[wid] = s;
    __syncthreads();
    s = 0.f;
    #pragma unroll
    for (int w = 0; w < 8; w++) s += shs[w];
    float inv = 1.0f / s;
    #pragma unroll
    for (int i = 0; i < 16; i++)
        p[threadIdx.x + i * 256] = __float2half(v[i] * inv);
}

// ============================================================
extern "C" void kernel_launch(void* const* d_in, const int* in_sizes, int n_in,
                              void* d_out, int out_size) {
    const float* x     = (const float*)d_in[0];
    const float* gamma = (const float*)d_in[1];
    const float* beta  = (const float*)d_in[2];
    const float* qkv_w = (const float*)d_in[3];
    const float* qkv_b = (const float*)d_in[4];
    const float* out_w = (const float*)d_in[5];
    const float* out_b = (const float*)d_in[6];
    float* out = (float*)d_out;

    gn_kernel<<<Bb * Gg, 1024>>>(x, gamma, beta);

    tr_f2h<<<dim3(Cc / 32, 3 * Cc / 32), dim3(32, 8)>>>(qkv_w, OFF_WQ16, 3 * Cc, Cc);
    tr_f2h<<<dim3(Cc / 32, Cc / 32), dim3(32, 8)>>>(out_w, OFF_WO16, Cc, Cc);

    // qkv16 = Wq16 * xn16 + b    (M=768, N=4096, K=256) -> fp16
    gemm_h<<<dim3(Nn / BN, 3 * Cc / BM, Bb), 256>>>(
        OFF_WQ16, OFF_XN16, OFF_QKV16, nullptr,
        3 * Cc, Nn, Cc,
        0, (size_t)Cc * Nn, (size_t)3 * Cc * Nn,
        qkv_b, nullptr, 0, 1.0f, 0);

    // S = (Q^T K)/16   (M=N=4096, K=256) -> fp32 g_S
    gemm_h<<<dim3(Nn / BN, Nn / BM, Bb), 256>>>(
        OFF_QKV16, OFF_QKV16 + (size_t)Cc * Nn, 0, nullptr,
        Nn, Nn, Cc,
        (size_t)3 * Cc * Nn, (size_t)3 * Cc * Nn, 0,
        nullptr, nullptr, 0, 0.0625f, 1);

    softmax_kernel<<<dim3(Nn, Bb), 256>>>();

    // Vt16 [j][c] from qkv16 V part [c][j]
    tr_h2h<<<dim3(Nn / 32, Cc / 32, Bb), dim3(32, 8)>>>(
        OFF_QKV16 + (size_t)2 * Cc * Nn, OFF_VT16,
        Cc, Nn, (size_t)3 * Cc * Nn, (size_t)Nn * Cc);

    // ao16 = P16 * Vt16    (M=256, N=4096, K=4096)
    gemm_av_h<<<dim3(Nn / BN, Cc / BM, Bb), 256>>>();

    // out = Wo16 * ao16 + b + x   (M=256, N=4096, K=256) -> fp32 ext
    gemm_h<<<dim3(Nn / BN, Cc / BM, Bb), 256>>>(
        OFF_WO16, OFF_AO16, 0, out,
        Cc, Nn, Cc,
        0, (size_t)Cc * Nn, (size_t)Cc * Nn,
        out_b, x, (size_t)Cc * Nn, 1.0f, 2);
}

// round 10
// speedup vs baseline: 6.0237x; 1.0032x over previous
#include <cuda_runtime.h>
#include <cuda_fp16.h>
#include <cstdint>

#define Bb 4
#define Cc 256
#define Nn 4096
#define Gg 8
#define CPG 32
#define GSIZE (CPG*Nn)
#define EPSf 1e-5f

// ---- fp16 arena (halfs) ----
#define OFF_XN16   ((size_t)0)
#define OFF_QKV16  (OFF_XN16  + (size_t)Bb*Cc*Nn)
#define OFF_P16    (OFF_QKV16 + (size_t)Bb*3*Cc*Nn)
#define OFF_AO16   (OFF_P16   + (size_t)Bb*Nn*Nn)
#define OFF_WQ16   (OFF_AO16  + (size_t)Bb*Cc*Nn)
#define OFF_WO16   (OFF_WQ16  + (size_t)Cc*3*Cc)
#define H_SZ       (OFF_WO16  + (size_t)Cc*Cc)

__device__ __align__(16) __half g_h[H_SZ];

// ============================================================
// PTX macros
// ============================================================
#define CPA16(smem_u32, gptr) \
    asm volatile("cp.async.cg.shared.global [%0], [%1], 16;" \
                 :: "r"(smem_u32), "l"(gptr))
#define CP_COMMIT() asm volatile("cp.async.commit_group;")
#define CP_WAIT(n)  asm volatile("cp.async.wait_group %0;" :: "n"(n))

#define LDSM4T(R, addr) \
    asm volatile("ldmatrix.sync.aligned.m8n8.x4.trans.shared.b16 {%0,%1,%2,%3}, [%4];" \
        : "=r"((R)[0]), "=r"((R)[1]), "=r"((R)[2]), "=r"((R)[3]) : "r"(addr))
#define LDSM4N(R, addr) \
    asm volatile("ldmatrix.sync.aligned.m8n8.x4.shared.b16 {%0,%1,%2,%3}, [%4];" \
        : "=r"((R)[0]), "=r"((R)[1]), "=r"((R)[2]), "=r"((R)[3]) : "r"(addr))

#define MMA16(C, A, B) \
    asm volatile( \
        "mma.sync.aligned.m16n8k16.row.col.f32.f16.f16.f32 " \
        "{%0,%1,%2,%3},{%4,%5,%6,%7},{%8,%9},{%0,%1,%2,%3};" \
        : "+f"((C)[0]), "+f"((C)[1]), "+f"((C)[2]), "+f"((C)[3]) \
        : "r"((A)[0]), "r"((A)[1]), "r"((A)[2]), "r"((A)[3]), \
          "r"((B)[0]), "r"((B)[1]))

// ============================================================
// GroupNorm -> fp16 xn
// ============================================================
__global__ void gn_kernel(const float* __restrict__ x,
                          const float* __restrict__ gamma,
                          const float* __restrict__ beta) {
    int bg = blockIdx.x;
    int b = bg / Gg, g = bg % Gg;
    size_t base = ((size_t)b * Cc + (size_t)g * CPG) * Nn;
    const float* xp = x + base;

    float s = 0.f, ss = 0.f;
    for (int i = threadIdx.x; i < GSIZE; i += blockDim.x) {
        float v = xp[i];
        s += v; ss += v * v;
    }
    __shared__ float sh_s[32], sh_ss[32];
    #pragma unroll
    for (int o = 16; o; o >>= 1) {
        s  += __shfl_down_sync(0xffffffffu, s,  o);
        ss += __shfl_down_sync(0xffffffffu, ss, o);
    }
    int wid = threadIdx.x >> 5, lid = threadIdx.x & 31;
    if (lid == 0) { sh_s[wid] = s; sh_ss[wid] = ss; }
    __syncthreads();
    int nw = blockDim.x >> 5;
    if (wid == 0) {
        s  = (lid < nw) ? sh_s[lid]  : 0.f;
        ss = (lid < nw) ? sh_ss[lid] : 0.f;
        #pragma unroll
        for (int o = 16; o; o >>= 1) {
            s  += __shfl_down_sync(0xffffffffu, s,  o);
            ss += __shfl_down_sync(0xffffffffu, ss, o);
        }
        if (lid == 0) { sh_s[0] = s; sh_ss[0] = ss; }
    }
    __syncthreads();
    float mean = sh_s[0] * (1.0f / GSIZE);
    float var  = sh_ss[0] * (1.0f / GSIZE) - mean * mean;
    float rstd = rsqrtf(var + EPSf);

    __half* op = g_h + OFF_XN16 + base;
    for (int i = threadIdx.x; i < GSIZE; i += blockDim.x) {
        int ch = g * CPG + i / Nn;
        op[i] = __float2half((xp[i] - mean) * rstd * gamma[ch] + beta[ch]);
    }
}

// ============================================================
// transpose fp32 ext [M][K] -> fp16 arena [K][M]
// ============================================================
__global__ void tr_f2h(const float* __restrict__ in, size_t outOff, int M, int K) {
    __shared__ float t[32][33];
    int k0 = blockIdx.x * 32, m0 = blockIdx.y * 32;
    int tx = threadIdx.x, ty = threadIdx.y;
    #pragma unroll
    for (int i = ty; i < 32; i += 8)
        t[i][tx] = in[(size_t)(m0 + i) * K + k0 + tx];
    __syncthreads();
    __half* op = g_h + outOff;
    #pragma unroll
    for (int i = ty; i < 32; i += 8)
        op[(size_t)(k0 + i) * M + m0 + tx] = __float2half(t[tx][i]);
}

// ============================================================
// fp16 GEMM (A-trans [k][m], B-trans [k][n]), 5-stage pipeline
//   modes: 0 -> fp16 arena (+bias); 1 -> fp16 arena (*scale);
//          2 -> fp32 ext (+bias +res)
//   CTA 128x128x16, 8 warps of 64x32.
// ============================================================
#define BM 128
#define BN 128
#define HLD 136

#define H_LOAD(buf, kk) do {                                                   \
    uint32_t sa_ = (uint32_t)__cvta_generic_to_shared(&Sh[buf][0][0][0]);      \
    uint32_t sb_ = (uint32_t)__cvta_generic_to_shared(&Sh[buf][1][0][0]);      \
    int k_ = tid >> 4, q_ = tid & 15;                                          \
    CPA16(sa_ + (uint32_t)(k_ * HLD + q_ * 8) * 2,                             \
          Ap + (size_t)((kk) + k_) * M + bm + q_ * 8);                         \
    CPA16(sb_ + (uint32_t)(k_ * HLD + q_ * 8) * 2,                             \
          Bp + (size_t)((kk) + k_) * N + bn + q_ * 8);                         \
    CP_COMMIT();                                                               \
} while (0)

__global__ __launch_bounds__(256) void gemm_h(
    size_t aOff, size_t bOff, size_t cOff, float* Cext,
    int M, int N, int K,
    size_t sA, size_t sB, size_t sC,
    const float* __restrict__ bias,
    const float* __restrict__ resExt, size_t sRes,
    float scale, int mode)
{
    __shared__ __half Sh[5][2][16][HLD];   // 43520 B

    int bz = blockIdx.z;
    const __half* Ap = g_h + aOff + (size_t)bz * sA;
    const __half* Bp = g_h + bOff + (size_t)bz * sB;
    int bm = blockIdx.y * BM, bn = blockIdx.x * BN;
    int tid = threadIdx.x, lane = tid & 31, wid = tid >> 5;
    int wm = (wid & 1) * 64, wn = (wid >> 1) * 32;

    float acc[4][4][4];
    #pragma unroll
    for (int i = 0; i < 4; i++)
        #pragma unroll
        for (int j = 0; j < 4; j++)
            #pragma unroll
            for (int r = 0; r < 4; r++) acc[i][j][r] = 0.f;

    int aRow = ((lane >> 4) << 3) + (lane & 7);
    int aCol = ((lane >> 3) & 1) * 8;
    int bRow = ((lane >> 3) & 1) * 8 + (lane & 7);
    int bCol = (lane >> 4) * 8;

    int steps = K / 16;                     // >= 16 for all uses
    H_LOAD(0, 0); H_LOAD(1, 16); H_LOAD(2, 32); H_LOAD(3, 48);

    for (int it = 0; it < steps; it++) {
        CP_WAIT(3);
        __syncthreads();
        int cur = it % 5;
        if (it + 4 < steps) {
            int nb = (it + 4) % 5, kk = (it + 4) * 16;
            H_LOAD(nb, kk);
        }
        uint32_t sa = (uint32_t)__cvta_generic_to_shared(&Sh[cur][0][0][0]);
        uint32_t sb = (uint32_t)__cvta_generic_to_shared(&Sh[cur][1][0][0]);

        uint32_t a[4][4], b[4][2];
        #pragma unroll
        for (int mt = 0; mt < 4; mt++) {
            uint32_t ad = sa + (uint32_t)(aRow * HLD + wm + mt * 16 + aCol) * 2;
            LDSM4T(a[mt], ad);
        }
        #pragma unroll
        for (int np = 0; np < 2; np++) {
            uint32_t bd = sb + (uint32_t)(bRow * HLD + wn + np * 16 + bCol) * 2;
            uint32_t rr[4];
            LDSM4T(rr, bd);
            b[np * 2][0] = rr[0]; b[np * 2][1] = rr[1];
            b[np * 2 + 1][0] = rr[2]; b[np * 2 + 1][1] = rr[3];
        }
        #pragma unroll
        for (int mt = 0; mt < 4; mt++)
            #pragma unroll
            for (int nt = 0; nt < 4; nt++)
                MMA16(acc[mt][nt], a[mt], b[nt]);
    }

    // epilogue
    #pragma unroll
    for (int mt = 0; mt < 4; mt++) {
        int r0 = bm + wm + mt * 16 + (lane >> 2);
        float b0f = (mode != 1 && bias) ? bias[r0] : 0.f;
        float b1f = (mode != 1 && bias) ? bias[r0 + 8] : 0.f;
        #pragma unroll
        for (int nt = 0; nt < 4; nt++) {
            int cc = bn + wn + nt * 8 + 2 * (lane & 3);
            float v0 = acc[mt][nt][0], v1 = acc[mt][nt][1];
            float v2 = acc[mt][nt][2], v3 = acc[mt][nt][3];
            if (mode == 0) {
                __half* Ch = g_h + cOff + (size_t)bz * sC;
                *(__half2*)&Ch[(size_t)r0 * N + cc] =
                    __floats2half2_rn(v0 + b0f, v1 + b0f);
                *(__half2*)&Ch[(size_t)(r0 + 8) * N + cc] =
                    __floats2half2_rn(v2 + b1f, v3 + b1f);
            } else if (mode == 1) {
                __half* Ch = g_h + cOff + (size_t)bz * sC;
                *(__half2*)&Ch[(size_t)r0 * N + cc] =
                    __floats2half2_rn(v0 * scale, v1 * scale);
                *(__half2*)&Ch[(size_t)(r0 + 8) * N + cc] =
                    __floats2half2_rn(v2 * scale, v3 * scale);
            } else {
                float* Cp = Cext + (size_t)bz * sC;
                const float* rp = resExt + (size_t)bz * sRes;
                float2 ra = *(const float2*)&rp[(size_t)r0 * N + cc];
                float2 rb = *(const float2*)&rp[(size_t)(r0 + 8) * N + cc];
                *(float2*)&Cp[(size_t)r0 * N + cc] =
                    make_float2(v0 + b0f + ra.x, v1 + b0f + ra.y);
                *(float2*)&Cp[(size_t)(r0 + 8) * N + cc] =
                    make_float2(v2 + b1f + rb.x, v3 + b1f + rb.y);
            }
        }
    }
}

// ============================================================
// attn*V:  ao[c][i] = sum_j V[c][j] * P[i][j]
//   A = V [m=c][k=j] row-major (non-trans ldmatrix, NO transpose pass)
//   B = P [n=i][k=j] (non-trans ldmatrix)
//   3-stage pipeline, CTA 128x128x16.
// ============================================================
#define PLD 24

#define AV_LOAD(buf, kk) do {                                                  \
    uint32_t sa_ = (uint32_t)__cvta_generic_to_shared(&Sv[buf][0][0][0]);      \
    uint32_t sp_ = (uint32_t)__cvta_generic_to_shared(&Sv[buf][1][0][0]);      \
    int r_ = tid >> 1, q_ = tid & 1;                                           \
    CPA16(sa_ + (uint32_t)(r_ * PLD + q_ * 8) * 2,                             \
          Vp + (size_t)(bm + r_) * Nn + (kk) + q_ * 8);                        \
    CPA16(sp_ + (uint32_t)(r_ * PLD + q_ * 8) * 2,                             \
          Pp + (size_t)(bn + r_) * Nn + (kk) + q_ * 8);                        \
    CP_COMMIT();                                                               \
} while (0)

__global__ __launch_bounds__(256) void gemm_av_h() {
    __shared__ __half Sv[3][2][128][PLD];   // 36864 B

    int bz = blockIdx.z;
    const __half* Vp = g_h + OFF_QKV16 + (size_t)bz * 3 * Cc * Nn + (size_t)2 * Cc * Nn;
    const __half* Pp = g_h + OFF_P16 + (size_t)bz * Nn * Nn;
    __half* Cp = g_h + OFF_AO16 + (size_t)bz * Cc * Nn;
    int bm = blockIdx.y * BM, bn = blockIdx.x * BN;
    int tid = threadIdx.x, lane = tid & 31, wid = tid >> 5;
    int wm = (wid & 1) * 64, wn = (wid >> 1) * 32;

    float acc[4][4][4];
    #pragma unroll
    for (int i = 0; i < 4; i++)
        #pragma unroll
        for (int j = 0; j < 4; j++)
            #pragma unroll
            for (int r = 0; r < 4; r++) acc[i][j][r] = 0.f;

    int vRow = ((lane >> 3) & 1) * 8 + (lane & 7);   // A non-trans
    int vCol = (lane >> 4) * 8;
    int pRow = (lane >> 4) * 8 + (lane & 7);         // B non-trans
    int pCol = ((lane >> 3) & 1) * 8;

    int steps = Nn / 16;                              // 256
    AV_LOAD(0, 0); AV_LOAD(1, 16);

    for (int it = 0; it < steps; it++) {
        CP_WAIT(1);
        __syncthreads();
        int cur = it % 3;
        if (it + 2 < steps) {
            int nb = (it + 2) % 3, kk = (it + 2) * 16;
            AV_LOAD(nb, kk);
        }
        uint32_t sa = (uint32_t)__cvta_generic_to_shared(&Sv[cur][0][0][0]);
        uint32_t sp = (uint32_t)__cvta_generic_to_shared(&Sv[cur][1][0][0]);

        uint32_t a[4][4], b[4][2];
        #pragma unroll
        for (int mt = 0; mt < 4; mt++) {
            uint32_t ad = sa + (uint32_t)((wm + mt * 16 + vRow) * PLD + vCol) * 2;
            LDSM4N(a[mt], ad);
        }
        #pragma unroll
        for (int np = 0; np < 2; np++) {
            uint32_t pd = sp + (uint32_t)((wn + np * 16 + pRow) * PLD + pCol) * 2;
            uint32_t rr[4];
            LDSM4N(rr, pd);
            b[np * 2][0] = rr[0]; b[np * 2][1] = rr[1];
            b[np * 2 + 1][0] = rr[2]; b[np * 2 + 1][1] = rr[3];
        }
        #pragma unroll
        for (int mt = 0; mt < 4; mt++)
            #pragma unroll
            for (int nt = 0; nt < 4; nt++)
                MMA16(acc[mt][nt], a[mt], b[nt]);
    }

    #pragma unroll
    for (int mt = 0; mt < 4; mt++) {
        int r0 = bm + wm + mt * 16 + (lane >> 2);
        #pragma unroll
        for (int nt = 0; nt < 4; nt++) {
            int cc = bn + wn + nt * 8 + 2 * (lane & 3);
            *(__half2*)&Cp[(size_t)r0 * Nn + cc] =
                __floats2half2_rn(acc[mt][nt][0], acc[mt][nt][1]);
            *(__half2*)&Cp[(size_t)(r0 + 8) * Nn + cc] =
                __floats2half2_rn(acc[mt][nt][2], acc[mt][nt][3]);
        }
    }
}

// ============================================================
// Softmax fp16 in-place on P16 rows (length 4096).
// ============================================================
__global__ void softmax_kernel() {
    __half2* r = (__half2*)(g_h + OFF_P16 +
                            ((size_t)blockIdx.y * Nn + blockIdx.x) * Nn);
    float2 v[8];
    float mx = -3.4e38f;
    #pragma unroll
    for (int i = 0; i < 8; i++) {
        v[i] = __half22float2(r[threadIdx.x + i * 256]);
        mx = fmaxf(mx, fmaxf(v[i].x, v[i].y));
    }
    __shared__ float sh[8];
    int wid = threadIdx.x >> 5, lid = threadIdx.x & 31;
    #pragma unroll
    for (int o = 16; o; o >>= 1) mx = fmaxf(mx, __shfl_xor_sync(0xffffffffu, mx, o));
    if (lid == 0) sh[wid] = mx;
    __syncthreads();
    mx = sh[0];
    #pragma unroll
    for (int w = 1; w < 8; w++) mx = fmaxf(mx, sh[w]);

    float s = 0.f;
    #pragma unroll
    for (int i = 0; i < 8; i++) {
        v[i].x = __expf(v[i].x - mx);
        v[i].y = __expf(v[i].y - mx);
        s += v[i].x + v[i].y;
    }
    #pragma unroll
    for (int o = 16; o; o >>= 1) s += __shfl_xor_sync(0xffffffffu, s, o);
    __shared__ float shs[8];
    if (lid == 0) shs[wid] = s;
    __syncthreads();
    s = 0.f;
    #pragma unroll
    for (int w = 0; w < 8; w++) s += shs[w];
    float inv = 1.0f / s;
    #pragma unroll
    for (int i = 0; i < 8; i++)
        r[threadIdx.x + i * 256] = __floats2half2_rn(v[i].x * inv, v[i].y * inv);
}

// ============================================================
extern "C" void kernel_launch(void* const* d_in, const int* in_sizes, int n_in,
                              void* d_out, int out_size) {
    const float* x     = (const float*)d_in[0];
    const float* gamma = (const float*)d_in[1];
    const float* beta  = (const float*)d_in[2];
    const float* qkv_w = (const float*)d_in[3];
    const float* qkv_b = (const float*)d_in[4];
    const float* out_w = (const float*)d_in[5];
    const float* out_b = (const float*)d_in[6];
    float* out = (float*)d_out;

    gn_kernel<<<Bb * Gg, 1024>>>(x, gamma, beta);

    tr_f2h<<<dim3(Cc / 32, 3 * Cc / 32), dim3(32, 8)>>>(qkv_w, OFF_WQ16, 3 * Cc, Cc);
    tr_f2h<<<dim3(Cc / 32, Cc / 32), dim3(32, 8)>>>(out_w, OFF_WO16, Cc, Cc);

    // qkv16 = Wq16 * xn16 + b    (M=768, N=4096, K=256) -> fp16
    gemm_h<<<dim3(Nn / BN, 3 * Cc / BM, Bb), 256>>>(
        OFF_WQ16, OFF_XN16, OFF_QKV16, nullptr,
        3 * Cc, Nn, Cc,
        0, (size_t)Cc * Nn, (size_t)3 * Cc * Nn,
        qkv_b, nullptr, 0, 1.0f, 0);

    // S16 = (Q^T K)/16   (M=N=4096, K=256) -> fp16 at P16
    gemm_h<<<dim3(Nn / BN, Nn / BM, Bb), 256>>>(
        OFF_QKV16, OFF_QKV16 + (size_t)Cc * Nn, OFF_P16, nullptr,
        Nn, Nn, Cc,
        (size_t)3 * Cc * Nn, (size_t)3 * Cc * Nn, (size_t)Nn * Nn,
        nullptr, nullptr, 0, 0.0625f, 1);

    softmax_kernel<<<dim3(Nn, Bb), 256>>>();

    // ao16 = P16 * V (no transpose pass)    (M=256, N=4096, K=4096)
    gemm_av_h<<<dim3(Nn / BN, Cc / BM, Bb), 256>>>();

    // out = Wo16 * ao16 + b + x   (M=256, N=4096, K=256) -> fp32 ext
    gemm_h<<<dim3(Nn / BN, Cc / BM, Bb), 256>>>(
        OFF_WO16, OFF_AO16, 0, out,
        Cc, Nn, Cc,
        0, (size_t)Cc * Nn, (size_t)Cc * Nn,
        out_b, x, (size_t)Cc * Nn, 1.0f, 2);
}

// round 11
// speedup vs baseline: 6.8621x; 1.1392x over previous
#include <cuda_runtime.h>
#include <cuda_fp16.h>
#include <cstdint>

#define Bb 4
#define Cc 256
#define Nn 4096
#define Gg 8
#define CPG 32
#define GSIZE (CPG*Nn)
#define EPSf 1e-5f

// ---- fp16 arena (halfs) ----
#define OFF_XN16   ((size_t)0)
#define OFF_QKV16  (OFF_XN16  + (size_t)Bb*Cc*Nn)
#define OFF_P16    (OFF_QKV16 + (size_t)Bb*3*Cc*Nn)
#define OFF_AO16   (OFF_P16   + (size_t)Bb*Nn*Nn)
#define OFF_WQ16   (OFF_AO16  + (size_t)Bb*Cc*Nn)
#define OFF_WO16   (OFF_WQ16  + (size_t)Cc*3*Cc)
#define H_SZ       (OFF_WO16  + (size_t)Cc*Cc)

__device__ __align__(16) __half g_h[H_SZ];
__device__ float g_stats[Bb*Gg*2];

// ============================================================
// PTX macros
// ============================================================
#define CPA16(smem_u32, gptr) \
    asm volatile("cp.async.cg.shared.global [%0], [%1], 16;" \
                 :: "r"(smem_u32), "l"(gptr))
#define CP_COMMIT() asm volatile("cp.async.commit_group;")
#define CP_WAIT(n)  asm volatile("cp.async.wait_group %0;" :: "n"(n))

#define LDSM4T(R, addr) \
    asm volatile("ldmatrix.sync.aligned.m8n8.x4.trans.shared.b16 {%0,%1,%2,%3}, [%4];" \
        : "=r"((R)[0]), "=r"((R)[1]), "=r"((R)[2]), "=r"((R)[3]) : "r"(addr))
#define LDSM4N(R, addr) \
    asm volatile("ldmatrix.sync.aligned.m8n8.x4.shared.b16 {%0,%1,%2,%3}, [%4];" \
        : "=r"((R)[0]), "=r"((R)[1]), "=r"((R)[2]), "=r"((R)[3]) : "r"(addr))

#define MMA16(C, A, B) \
    asm volatile( \
        "mma.sync.aligned.m16n8k16.row.col.f32.f16.f16.f32 " \
        "{%0,%1,%2,%3},{%4,%5,%6,%7},{%8,%9},{%0,%1,%2,%3};" \
        : "+f"((C)[0]), "+f"((C)[1]), "+f"((C)[2]), "+f"((C)[3]) \
        : "r"((A)[0]), "r"((A)[1]), "r"((A)[2]), "r"((A)[3]), \
          "r"((B)[0]), "r"((B)[1]))

// ============================================================
// GroupNorm, 3 passes (full-chip bandwidth)
// ============================================================
__global__ void gn_zero() {
    if (threadIdx.x < Bb * Gg * 2) g_stats[threadIdx.x] = 0.f;
}

__global__ void gn_part(const float* __restrict__ x) {
    int bg = blockIdx.x >> 3, sl = blockIdx.x & 7;
    const float4* xp = (const float4*)(x + (size_t)bg * GSIZE + (size_t)sl * (GSIZE / 8));
    const int n4 = GSIZE / 8 / 4;   // 4096
    float s = 0.f, ss = 0.f;
    for (int i = threadIdx.x; i < n4; i += blockDim.x) {
        float4 v = xp[i];
        s  += v.x + v.y + v.z + v.w;
        ss += v.x * v.x + v.y * v.y + v.z * v.z + v.w * v.w;
    }
    __shared__ float sh_s[8], sh_ss[8];
    int wid = threadIdx.x >> 5, lid = threadIdx.x & 31;
    #pragma unroll
    for (int o = 16; o; o >>= 1) {
        s  += __shfl_down_sync(0xffffffffu, s,  o);
        ss += __shfl_down_sync(0xffffffffu, ss, o);
    }
    if (lid == 0) { sh_s[wid] = s; sh_ss[wid] = ss; }
    __syncthreads();
    if (threadIdx.x == 0) {
        float ts = 0.f, tss = 0.f;
        #pragma unroll
        for (int w = 0; w < 8; w++) { ts += sh_s[w]; tss += sh_ss[w]; }
        atomicAdd(&g_stats[bg * 2], ts);
        atomicAdd(&g_stats[bg * 2 + 1], tss);
    }
}

__global__ void gn_apply(const float* __restrict__ x,
                         const float* __restrict__ gamma,
                         const float* __restrict__ beta) {
    const size_t total4 = (size_t)Bb * Cc * Nn / 4;   // 4,194,304
    size_t stride = (size_t)gridDim.x * blockDim.x;
    for (size_t i4 = (size_t)blockIdx.x * blockDim.x + threadIdx.x;
         i4 < total4; i4 += stride) {
        size_t idx = i4 * 4;
        int c_glob = (int)(idx / Nn);          // b*Cc + c
        int c = c_glob % Cc;
        int bg = (c_glob / Cc) * Gg + c / CPG;
        float mean = g_stats[bg * 2] * (1.0f / GSIZE);
        float var  = g_stats[bg * 2 + 1] * (1.0f / GSIZE) - mean * mean;
        float rstd = rsqrtf(var + EPSf);
        float gm = gamma[c] * rstd, bt = beta[c] - mean * rstd * gamma[c];
        float4 v = *(const float4*)(x + idx);
        __half2 h0 = __floats2half2_rn(v.x * gm + bt, v.y * gm + bt);
        __half2 h1 = __floats2half2_rn(v.z * gm + bt, v.w * gm + bt);
        *(__half2*)(g_h + OFF_XN16 + idx)     = h0;
        *(__half2*)(g_h + OFF_XN16 + idx + 2) = h1;
    }
}

// ============================================================
// transpose fp32 ext [M][K] -> fp16 arena [K][M]
// ============================================================
__global__ void tr_f2h(const float* __restrict__ in, size_t outOff, int M, int K) {
    __shared__ float t[32][33];
    int k0 = blockIdx.x * 32, m0 = blockIdx.y * 32;
    int tx = threadIdx.x, ty = threadIdx.y;
    #pragma unroll
    for (int i = ty; i < 32; i += 8)
        t[i][tx] = in[(size_t)(m0 + i) * K + k0 + tx];
    __syncthreads();
    __half* op = g_h + outOff;
    #pragma unroll
    for (int i = ty; i < 32; i += 8)
        op[(size_t)(k0 + i) * M + m0 + tx] = __float2half(t[tx][i]);
}

// ============================================================
// fp16 GEMM (A-trans [k][m], B-trans [k][n])
//   4-stage x 32k pipeline, 2 subchunks/iter, 1 sync/iter.
//   modes: 0 fp16+bias; 1 fp16*scale; 2 fp32 ext +bias+res
// ============================================================
#define BM 128
#define BN 128
#define HLD 136
#define STG_H (2*32*HLD)            // halfs per stage (A+B)
#define SMEM_H_BYTES (4*STG_H*2)    // 69632

#define H_LOAD(buf, kk) do {                                                   \
    uint32_t sa_ = smb + (uint32_t)((buf) * STG_H) * 2;                        \
    uint32_t sb_ = sa_ + (uint32_t)(32 * HLD) * 2;                             \
    int k_ = tid >> 4, q_ = tid & 15;                                          \
    CPA16(sa_ + (uint32_t)(k_ * HLD + q_ * 8) * 2,                             \
          Ap + (size_t)((kk) + k_) * M + bm + q_ * 8);                         \
    CPA16(sa_ + (uint32_t)((k_ + 16) * HLD + q_ * 8) * 2,                      \
          Ap + (size_t)((kk) + k_ + 16) * M + bm + q_ * 8);                    \
    CPA16(sb_ + (uint32_t)(k_ * HLD + q_ * 8) * 2,                             \
          Bp + (size_t)((kk) + k_) * N + bn + q_ * 8);                         \
    CPA16(sb_ + (uint32_t)((k_ + 16) * HLD + q_ * 8) * 2,                      \
          Bp + (size_t)((kk) + k_ + 16) * N + bn + q_ * 8);                    \
    CP_COMMIT();                                                               \
} while (0)

__global__ __launch_bounds__(256, 2) void gemm_h(
    size_t aOff, size_t bOff, size_t cOff, float* Cext,
    int M, int N, int K,
    size_t sA, size_t sB, size_t sC,
    const float* __restrict__ bias,
    const float* __restrict__ resExt, size_t sRes,
    float scale, int mode)
{
    extern __shared__ __half sm[];
    uint32_t smb = (uint32_t)__cvta_generic_to_shared(sm);

    int bz = blockIdx.z;
    const __half* Ap = g_h + aOff + (size_t)bz * sA;
    const __half* Bp = g_h + bOff + (size_t)bz * sB;
    int bm = blockIdx.y * BM, bn = blockIdx.x * BN;
    int tid = threadIdx.x, lane = tid & 31, wid = tid >> 5;
    int wm = (wid & 1) * 64, wn = (wid >> 1) * 32;

    float acc[4][4][4];
    #pragma unroll
    for (int i = 0; i < 4; i++)
        #pragma unroll
        for (int j = 0; j < 4; j++)
            #pragma unroll
            for (int r = 0; r < 4; r++) acc[i][j][r] = 0.f;

    int aRow = ((lane >> 4) << 3) + (lane & 7);
    int aCol = ((lane >> 3) & 1) * 8;
    int bRow = ((lane >> 3) & 1) * 8 + (lane & 7);
    int bCol = (lane >> 4) * 8;

    int steps = K / 32;                 // >= 8 everywhere
    H_LOAD(0, 0); H_LOAD(1, 32); H_LOAD(2, 64);

    for (int it = 0; it < steps; it++) {
        CP_WAIT(2);
        __syncthreads();
        if (it + 3 < steps) { H_LOAD((it + 3) & 3, (it + 3) * 32); }
        else                { CP_COMMIT(); }

        uint32_t sa = smb + (uint32_t)((it & 3) * STG_H) * 2;
        uint32_t sb = sa + (uint32_t)(32 * HLD) * 2;

        #pragma unroll
        for (int sc = 0; sc < 2; sc++) {
            uint32_t a[4][4], b[4][2];
            #pragma unroll
            for (int mt = 0; mt < 4; mt++) {
                uint32_t ad = sa + (uint32_t)((sc * 16 + aRow) * HLD + wm + mt * 16 + aCol) * 2;
                LDSM4T(a[mt], ad);
            }
            #pragma unroll
            for (int np = 0; np < 2; np++) {
                uint32_t bd = sb + (uint32_t)((sc * 16 + bRow) * HLD + wn + np * 16 + bCol) * 2;
                uint32_t rr[4];
                LDSM4T(rr, bd);
                b[np * 2][0] = rr[0]; b[np * 2][1] = rr[1];
                b[np * 2 + 1][0] = rr[2]; b[np * 2 + 1][1] = rr[3];
            }
            #pragma unroll
            for (int mt = 0; mt < 4; mt++)
                #pragma unroll
                for (int nt = 0; nt < 4; nt++)
                    MMA16(acc[mt][nt], a[mt], b[nt]);
        }
    }

    // epilogue
    #pragma unroll
    for (int mt = 0; mt < 4; mt++) {
        int r0 = bm + wm + mt * 16 + (lane >> 2);
        float b0f = (mode != 1 && bias) ? bias[r0] : 0.f;
        float b1f = (mode != 1 && bias) ? bias[r0 + 8] : 0.f;
        #pragma unroll
        for (int nt = 0; nt < 4; nt++) {
            int cc = bn + wn + nt * 8 + 2 * (lane & 3);
            float v0 = acc[mt][nt][0], v1 = acc[mt][nt][1];
            float v2 = acc[mt][nt][2], v3 = acc[mt][nt][3];
            if (mode == 0) {
                __half* Ch = g_h + cOff + (size_t)bz * sC;
                *(__half2*)&Ch[(size_t)r0 * N + cc] =
                    __floats2half2_rn(v0 + b0f, v1 + b0f);
                *(__half2*)&Ch[(size_t)(r0 + 8) * N + cc] =
                    __floats2half2_rn(v2 + b1f, v3 + b1f);
            } else if (mode == 1) {
                __half* Ch = g_h + cOff + (size_t)bz * sC;
                *(__half2*)&Ch[(size_t)r0 * N + cc] =
                    __floats2half2_rn(v0 * scale, v1 * scale);
                *(__half2*)&Ch[(size_t)(r0 + 8) * N + cc] =
                    __floats2half2_rn(v2 * scale, v3 * scale);
            } else {
                float* Cp = Cext + (size_t)bz * sC;
                const float* rp = resExt + (size_t)bz * sRes;
                float2 ra = *(const float2*)&rp[(size_t)r0 * N + cc];
                float2 rb = *(const float2*)&rp[(size_t)(r0 + 8) * N + cc];
                *(float2*)&Cp[(size_t)r0 * N + cc] =
                    make_float2(v0 + b0f + ra.x, v1 + b0f + ra.y);
                *(float2*)&Cp[(size_t)(r0 + 8) * N + cc] =
                    make_float2(v2 + b1f + rb.x, v3 + b1f + rb.y);
            }
        }
    }
}

// ============================================================
// attn*V:  ao[c][i] = sum_j V[c][j] * P[i][j]
//   A = V [m=c][k=j] (non-trans), B = P [n=i][k=j] (non-trans)
//   4-stage x 32k, 2 subchunks/iter.
// ============================================================
#define PLD 40
#define STG_V (2*128*PLD)            // halfs per stage
#define SMEM_V_BYTES (4*STG_V*2)     // 81920

#define AV_LOAD(buf, kk) do {                                                  \
    uint32_t sv_ = smb + (uint32_t)((buf) * STG_V) * 2;                        \
    uint32_t sp_ = sv_ + (uint32_t)(128 * PLD) * 2;                            \
    int r_ = tid >> 2, q_ = tid & 3;                                           \
    CPA16(sv_ + (uint32_t)(r_ * PLD + q_ * 8) * 2,                             \
          Vp + (size_t)(bm + r_) * Nn + (kk) + q_ * 8);                        \
    CPA16(sv_ + (uint32_t)((r_ + 64) * PLD + q_ * 8) * 2,                      \
          Vp + (size_t)(bm + r_ + 64) * Nn + (kk) + q_ * 8);                   \
    CPA16(sp_ + (uint32_t)(r_ * PLD + q_ * 8) * 2,                             \
          Pp + (size_t)(bn + r_) * Nn + (kk) + q_ * 8);                        \
    CPA16(sp_ + (uint32_t)((r_ + 64) * PLD + q_ * 8) * 2,                      \
          Pp + (size_t)(bn + r_ + 64) * Nn + (kk) + q_ * 8);                   \
    CP_COMMIT();                                                               \
} while (0)

__global__ __launch_bounds__(256, 2) void gemm_av_h() {
    extern __shared__ __half sm[];
    uint32_t smb = (uint32_t)__cvta_generic_to_shared(sm);

    int bz = blockIdx.z;
    const __half* Vp = g_h + OFF_QKV16 + (size_t)bz * 3 * Cc * Nn + (size_t)2 * Cc * Nn;
    const __half* Pp = g_h + OFF_P16 + (size_t)bz * Nn * Nn;
    __half* Cp = g_h + OFF_AO16 + (size_t)bz * Cc * Nn;
    int bm = blockIdx.y * BM, bn = blockIdx.x * BN;
    int tid = threadIdx.x, lane = tid & 31, wid = tid >> 5;
    int wm = (wid & 1) * 64, wn = (wid >> 1) * 32;

    float acc[4][4][4];
    #pragma unroll
    for (int i = 0; i < 4; i++)
        #pragma unroll
        for (int j = 0; j < 4; j++)
            #pragma unroll
            for (int r = 0; r < 4; r++) acc[i][j][r] = 0.f;

    int vRow = ((lane >> 3) & 1) * 8 + (lane & 7);
    int vCol = (lane >> 4) * 8;
    int pRow = (lane >> 4) * 8 + (lane & 7);
    int pCol = ((lane >> 3) & 1) * 8;

    int steps = Nn / 32;                 // 128
    AV_LOAD(0, 0); AV_LOAD(1, 32); AV_LOAD(2, 64);

    for (int it = 0; it < steps; it++) {
        CP_WAIT(2);
        __syncthreads();
        if (it + 3 < steps) { AV_LOAD((it + 3) & 3, (it + 3) * 32); }
        else                { CP_COMMIT(); }

        uint32_t sv = smb + (uint32_t)((it & 3) * STG_V) * 2;
        uint32_t sp = sv + (uint32_t)(128 * PLD) * 2;

        #pragma unroll
        for (int sc = 0; sc < 2; sc++) {
            uint32_t a[4][4], b[4][2];
            #pragma unroll
            for (int mt = 0; mt < 4; mt++) {
                uint32_t ad = sv + (uint32_t)((wm + mt * 16 + vRow) * PLD + sc * 16 + vCol) * 2;
                LDSM4N(a[mt], ad);
            }
            #pragma unroll
            for (int np = 0; np < 2; np++) {
                uint32_t pd = sp + (uint32_t)((wn + np * 16 + pRow) * PLD + sc * 16 + pCol) * 2;
                uint32_t rr[4];
                LDSM4N(rr, pd);
                b[np * 2][0] = rr[0]; b[np * 2][1] = rr[1];
                b[np * 2 + 1][0] = rr[2]; b[np * 2 + 1][1] = rr[3];
            }
            #pragma unroll
            for (int mt = 0; mt < 4; mt++)
                #pragma unroll
                for (int nt = 0; nt < 4; nt++)
                    MMA16(acc[mt][nt], a[mt], b[nt]);
        }
    }

    #pragma unroll
    for (int mt = 0; mt < 4; mt++) {
        int r0 = bm + wm + mt * 16 + (lane >> 2);
        #pragma unroll
        for (int nt = 0; nt < 4; nt++) {
            int cc = bn + wn + nt * 8 + 2 * (lane & 3);
            *(__half2*)&Cp[(size_t)r0 * Nn + cc] =
                __floats2half2_rn(acc[mt][nt][0], acc[mt][nt][1]);
            *(__half2*)&Cp[(size_t)(r0 + 8) * Nn + cc] =
                __floats2half2_rn(acc[mt][nt][2], acc[mt][nt][3]);
        }
    }
}

// ============================================================
// Softmax fp16 in-place on P16 rows (length 4096).
// ============================================================
__global__ void softmax_kernel() {
    __half2* r = (__half2*)(g_h + OFF_P16 +
                            ((size_t)blockIdx.y * Nn + blockIdx.x) * Nn);
    float2 v[8];
    float mx = -3.4e38f;
    #pragma unroll
    for (int i = 0; i < 8; i++) {
        v[i] = __half22float2(r[threadIdx.x + i * 256]);
        mx = fmaxf(mx, fmaxf(v[i].x, v[i].y));
    }
    __shared__ float sh[8];
    int wid = threadIdx.x >> 5, lid = threadIdx.x & 31;
    #pragma unroll
    for (int o = 16; o; o >>= 1) mx = fmaxf(mx, __shfl_xor_sync(0xffffffffu, mx, o));
    if (lid == 0) sh[wid] = mx;
    __syncthreads();
    mx = sh[0];
    #pragma unroll
    for (int w = 1; w < 8; w++) mx = fmaxf(mx, sh[w]);

    float s = 0.f;
    #pragma unroll
    for (int i = 0; i < 8; i++) {
        v[i].x = __expf(v[i].x - mx);
        v[i].y = __expf(v[i].y - mx);
        s += v[i].x + v[i].y;
    }
    #pragma unroll
    for (int o = 16; o; o >>= 1) s += __shfl_xor_sync(0xffffffffu, s, o);
    __shared__ float shs[8];
    if (lid == 0) shs[wid] = s;
    __syncthreads();
    s = 0.f;
    #pragma unroll
    for (int w = 0; w < 8; w++) s += shs[w];
    float inv = 1.0f / s;
    #pragma unroll
    for (int i = 0; i < 8; i++)
        r[threadIdx.x + i * 256] = __floats2half2_rn(v[i].x * inv, v[i].y * inv);
}

// ============================================================
extern "C" void kernel_launch(void* const* d_in, const int* in_sizes, int n_in,
                              void* d_out, int out_size) {
    const float* x     = (const float*)d_in[0];
    const float* gamma = (const float*)d_in[1];
    const float* beta  = (const float*)d_in[2];
    const float* qkv_w = (const float*)d_in[3];
    const float* qkv_b = (const float*)d_in[4];
    const float* out_w = (const float*)d_in[5];
    const float* out_b = (const float*)d_in[6];
    float* out = (float*)d_out;

    static bool attr_set = false;
    if (!attr_set) {
        cudaFuncSetAttribute(gemm_h, cudaFuncAttributeMaxDynamicSharedMemorySize,
                             SMEM_H_BYTES);
        cudaFuncSetAttribute(gemm_av_h, cudaFuncAttributeMaxDynamicSharedMemorySize,
                             SMEM_V_BYTES);
        attr_set = true;
    }

    gn_zero<<<1, 64>>>();
    gn_part<<<Bb * Gg * 8, 256>>>(x);
    gn_apply<<<4096, 256>>>(x, gamma, beta);

    tr_f2h<<<dim3(Cc / 32, 3 * Cc / 32), dim3(32, 8)>>>(qkv_w, OFF_WQ16, 3 * Cc, Cc);
    tr_f2h<<<dim3(Cc / 32, Cc / 32), dim3(32, 8)>>>(out_w, OFF_WO16, Cc, Cc);

    // qkv16 = Wq16 * xn16 + b    (M=768, N=4096, K=256)
    gemm_h<<<dim3(Nn / BN, 3 * Cc / BM, Bb), 256, SMEM_H_BYTES>>>(
        OFF_WQ16, OFF_XN16, OFF_QKV16, nullptr,
        3 * Cc, Nn, Cc,
        0, (size_t)Cc * Nn, (size_t)3 * Cc * Nn,
        qkv_b, nullptr, 0, 1.0f, 0);

    // S16 = (Q^T K)/16   (M=N=4096, K=256) -> fp16 at P16
    gemm_h<<<dim3(Nn / BN, Nn / BM, Bb), 256, SMEM_H_BYTES>>>(
        OFF_QKV16, OFF_QKV16 + (size_t)Cc * Nn, OFF_P16, nullptr,
        Nn, Nn, Cc,
        (size_t)3 * Cc * Nn, (size_t)3 * Cc * Nn, (size_t)Nn * Nn,
        nullptr, nullptr, 0, 0.0625f, 1);

    softmax_kernel<<<dim3(Nn, Bb), 256>>>();

    // ao16 = P16 * V     (M=256, N=4096, K=4096)
    gemm_av_h<<<dim3(Nn / BN, Cc / BM, Bb), 256, SMEM_V_BYTES>>>();

    // out = Wo16 * ao16 + b + x   (M=256, N=4096, K=256) -> fp32 ext
    gemm_h<<<dim3(Nn / BN, Cc / BM, Bb), 256, SMEM_H_BYTES>>>(
        OFF_WO16, OFF_AO16, 0, out,
        Cc, Nn, Cc,
        0, (size_t)Cc * Nn, (size_t)Cc * Nn,
        out_b, x, (size_t)Cc * Nn, 1.0f, 2);
}